// round 5
// baseline (speedup 1.0000x reference)
#include <cuda_runtime.h>
#include <math.h>
#include <stdint.h>

#define B_    4
#define LQ_   4096
#define LKV_  256
#define D_    1024
#define H_    16
#define KVH_  4
#define HD_   64
#define NF_MAX 4096

// ---------------- scratch (device globals; no allocation allowed) ----------
__device__ float g_P[(size_t)B_ * LQ_ * D_];            // tf32-rounded patches
__device__ float g_L[(size_t)B_ * LKV_ * D_];           // tf32-rounded latents
__device__ float g_Q[(size_t)B_ * LQ_ * D_];
__device__ float g_K[(size_t)B_ * LKV_ * KVH_ * HD_];
__device__ float g_V[(size_t)B_ * LKV_ * KVH_ * HD_];
__device__ float g_attn[(size_t)B_ * LQ_ * D_];         // tf32-rounded attn out
__device__ float g_WtQ[(size_t)D_ * D_];                // W^T [N][K], tf32-rounded
__device__ float g_WtK[(size_t)(KVH_ * HD_) * D_];
__device__ float g_WtV[(size_t)(KVH_ * HD_) * D_];
__device__ float g_WtO[(size_t)D_ * D_];
__device__ float g_rope[2 * NF_MAX * 32];               // cos | sin

// ---------------- helpers ---------------------------------------------------
__device__ __forceinline__ uint32_t smem_u32(const void* p) {
    uint32_t a;
    asm("{ .reg .u64 t; cvta.to.shared.u64 t, %1; cvt.u32.u64 %0, t; }"
        : "=r"(a) : "l"(p));
    return a;
}
__device__ __forceinline__ uint32_t sw128(uint32_t off) {
    return off ^ ((off >> 3) & 0x70);
}
__device__ __forceinline__ float to_tf32(float x) {
    uint32_t u;
    asm("cvt.rna.tf32.f32 %0, %1;" : "=r"(u) : "f"(x));
    return __uint_as_float(u);
}

#define CP_A16(d, s) \
    asm volatile("cp.async.cg.shared.global [%0], [%1], 16;" :: "r"(d), "l"(s) : "memory")
#define CP_COMMIT() asm volatile("cp.async.commit_group;" ::: "memory")
#define CP_WAIT1()  asm volatile("cp.async.wait_group 1;" ::: "memory")
#define CP_WAIT0()  asm volatile("cp.async.wait_group 0;" ::: "memory")
#define LDSM4(r, addr) \
    asm volatile("ldmatrix.sync.aligned.m8n8.x4.shared.b16 {%0,%1,%2,%3}, [%4];" \
        : "=r"((r)[0]), "=r"((r)[1]), "=r"((r)[2]), "=r"((r)[3]) : "r"(addr))
#define MMA_TF32(d, a0, a1, a2, a3, b0, b1) \
    asm volatile("mma.sync.aligned.m16n8k8.row.col.f32.tf32.tf32.f32 " \
        "{%0,%1,%2,%3}, {%4,%5,%6,%7}, {%8,%9}, {%0,%1,%2,%3};" \
        : "+f"((d)[0]), "+f"((d)[1]), "+f"((d)[2]), "+f"((d)[3]) \
        : "r"(a0), "r"(a1), "r"(a2), "r"(a3), "r"(b0), "r"(b1))

// ---------------------------------------------------------------------------
__global__ void cvt_tf32_kernel(const float* __restrict__ in, float* __restrict__ out, int n4)
{
    int i = blockIdx.x * blockDim.x + threadIdx.x;
    if (i >= n4) return;
    float4 v = reinterpret_cast<const float4*>(in)[i];
    v.x = to_tf32(v.x); v.y = to_tf32(v.y);
    v.z = to_tf32(v.z); v.w = to_tf32(v.w);
    reinterpret_cast<float4*>(out)[i] = v;
}

__global__ void transpose_kernel(const float* __restrict__ W, float* __restrict__ Wt,
                                 int K, int N)
{
    __shared__ float t[32][33];
    int nb = blockIdx.x * 32, kb = blockIdx.y * 32;
    int x = threadIdx.x, y = threadIdx.y;   // 32 x 8
#pragma unroll
    for (int i = 0; i < 32; i += 8)
        t[y + i][x] = W[(size_t)(kb + y + i) * N + nb + x];
    __syncthreads();
#pragma unroll
    for (int i = 0; i < 32; i += 8)
        Wt[(size_t)(nb + y + i) * K + kb + x] = to_tf32(t[x][y + i]);
}

__global__ void rope_table_kernel(const int* __restrict__ nf_ptr)
{
    int nf = *nf_ptr;
    if (nf <= 1 || nf > NF_MAX) return;
    int idx = blockIdx.x * blockDim.x + threadIdx.x;
    if (idx >= nf * 32) return;
    int j = idx & 31, pos = idx >> 5;
    float inv = powf(10000.0f, -(float)(2 * j) / 64.0f);
    float th = (float)pos * inv;
    g_rope[idx] = cosf(th);
    g_rope[NF_MAX * 32 + idx] = sinf(th);
}

// ---------------------------------------------------------------------------
// tf32 mma.sync GEMM: C[M,N] = A[M,K] @ Bt[N,K]^T + bias
// CTA tile 128x256xK, warp tile 64x64, BK=32, 3-stage cp.async pipeline,
// one __syncthreads per iteration. grid(N/256, M/128), 256 threads.
// Requires N % 256 == 0.
// ---------------------------------------------------------------------------
#define GSTAGE 49152u            // 16KB A + 32KB B per stage
#define GEMM_SMEM (3 * 49152)

__device__ __forceinline__ void load_tile256(const float* Ag, const float* Bg, int K,
                                             uint32_t buf, int tid)
{
    uint32_t aBuf = buf, bBuf = buf + 16384u;
#pragma unroll
    for (int j = 0; j < 4; j++) {
        int idx = j * 256 + tid;
        int row = idx >> 3, k4 = idx & 7;
        uint32_t off = sw128((uint32_t)(row * 128 + k4 * 16));
        CP_A16(aBuf + off, Ag + (size_t)row * K + k4 * 4);
    }
#pragma unroll
    for (int j = 0; j < 8; j++) {
        int idx = j * 256 + tid;
        int row = idx >> 3, k4 = idx & 7;
        uint32_t off = sw128((uint32_t)(row * 128 + k4 * 16));
        CP_A16(bBuf + off, Bg + (size_t)row * K + k4 * 4);
    }
}

__global__ __launch_bounds__(256)
void gemm_tf32(const float* __restrict__ A, const float* __restrict__ Bt,
               const float* __restrict__ bias, float* __restrict__ C,
               int M, int N, int K)
{
    extern __shared__ char smraw[];
    uint32_t data = smem_u32(smraw);   // 1024-aligned (148KB dynamic alloc)

    int tid = threadIdx.x, lane = tid & 31, wid = tid >> 5;
    int wm = (wid >> 2) * 64;   // 2 warp rows
    int wn = (wid & 3) * 64;    // 4 warp cols x 64

    const float* Ag = A  + (size_t)blockIdx.y * 128 * K;
    const float* Bg = Bt + (size_t)blockIdx.x * 256 * K;

    float acc[4][8][4];
#pragma unroll
    for (int i = 0; i < 4; i++)
#pragma unroll
        for (int j = 0; j < 8; j++)
#pragma unroll
            for (int k = 0; k < 4; k++) acc[i][j][k] = 0.f;

    int T = K >> 5;

    // prologue: stages 0,1
    load_tile256(Ag, Bg, K, data, tid);
    CP_COMMIT();
    if (T > 1) load_tile256(Ag + 32, Bg + 32, K, data + GSTAGE, tid);
    CP_COMMIT();   // commit even if empty (keeps group accounting uniform)

    int lmat = lane >> 3, lrow = lane & 7;
    int frow = ((lmat & 2) ? 8 : 0) + lrow;
    int fcol = (lmat & 1) * 16;

    int stage = 0;
    for (int t = 0; t < T; ++t) {
        CP_WAIT1();          // stage t resident (own thread)
        __syncthreads();     // visible to all; also frees stage (t+2)%3

        if (t + 2 < T) {
            uint32_t nb = data + (uint32_t)((stage + 2) % 3) * GSTAGE;
            load_tile256(Ag + (t + 2) * 32, Bg + (t + 2) * 32, K, nb, tid);
        }
        CP_COMMIT();

        uint32_t aB = data + (uint32_t)stage * GSTAGE;
        uint32_t bB = aB + 16384u;
#pragma unroll
        for (int kk = 0; kk < 4; ++kk) {
            uint32_t af[4][4], bf[4][4];
#pragma unroll
            for (int mi = 0; mi < 4; ++mi) {
                uint32_t addr = aB + sw128((uint32_t)((wm + mi * 16 + frow) * 128 + kk * 32 + fcol));
                LDSM4(af[mi], addr);
            }
#pragma unroll
            for (int nj = 0; nj < 4; ++nj) {
                uint32_t addr = bB + sw128((uint32_t)((wn + nj * 16 + frow) * 128 + kk * 32 + fcol));
                LDSM4(bf[nj], addr);
            }
#pragma unroll
            for (int mi = 0; mi < 4; ++mi)
#pragma unroll
                for (int ni = 0; ni < 8; ++ni) {
                    int nj = ni >> 1, lh = (ni & 1) * 2;
                    MMA_TF32(acc[mi][ni],
                             af[mi][0], af[mi][2], af[mi][1], af[mi][3],
                             bf[nj][lh], bf[nj][lh + 1]);
                }
        }
        stage = (stage + 1) % 3;
    }

    int rbase = blockIdx.y * 128 + wm + (lane >> 2);
    int cbase = blockIdx.x * 256 + wn + (lane & 3) * 2;
#pragma unroll
    for (int mi = 0; mi < 4; ++mi) {
#pragma unroll
        for (int ni = 0; ni < 8; ++ni) {
            int c = cbase + ni * 8;
            float2 bv = *(const float2*)(bias + c);
            int r0 = rbase + mi * 16;
            float2 v0 = { acc[mi][ni][0] + bv.x, acc[mi][ni][1] + bv.y };
            *(float2*)(C + (size_t)r0 * N + c) = v0;
            float2 v1 = { acc[mi][ni][2] + bv.x, acc[mi][ni][3] + bv.y };
            *(float2*)(C + (size_t)(r0 + 8) * N + c) = v1;
        }
    }
}

// ---------------------------------------------------------------------------
// MMA flash attention with fused RoPE (unchanged from round 4).
// ---------------------------------------------------------------------------
#define QS_OFF 0u
#define KS_OFF 32768u
#define VT_OFF 98304u
#define PS_OFF 163840u
#define ATTN_SMEM 229376

__global__ __launch_bounds__(256, 1)
void attn_kernel(const float* __restrict__ Q, const float* __restrict__ Kg,
                 const float* __restrict__ Vg, float* __restrict__ O,
                 const int* __restrict__ nf_ptr)
{
    extern __shared__ char sm[];
    uint32_t smb = smem_u32(sm);

    int tid = threadIdx.x, l = tid & 31, w = tid >> 5;
    int b = blockIdx.z, h = blockIdx.y, qt = blockIdx.x;
    int kvh = h >> 2;
    int nf = *nf_ptr;
    bool rope = (nf > 1) && (nf <= NF_MAX);
    int qdiv = rope ? (LQ_ / nf) : 1;
    int kdiv = rope ? (LKV_ / nf) : 1;

    {
        int row = tid >> 1, part = tid & 1;
        int qglob = qt * 128 + row;
        const float* src = Q + ((size_t)(b * LQ_ + qglob)) * D_ + h * HD_;
        int pos = rope ? (qglob / qdiv) : 0;
        const float* ct = g_rope + pos * 32;
        const float* st = g_rope + NF_MAX * 32 + pos * 32;
#pragma unroll
        for (int jj = 0; jj < 4; jj++) {
            int j = part * 16 + jj * 4;
            float4 x1 = *(const float4*)(src + j);
            float4 x2 = *(const float4*)(src + j + 32);
            float y1[4], y2[4];
            float a1[4] = {x1.x, x1.y, x1.z, x1.w};
            float a2[4] = {x2.x, x2.y, x2.z, x2.w};
#pragma unroll
            for (int e = 0; e < 4; e++) {
                float c = 1.f, s = 0.f;
                if (rope) { c = ct[j + e]; s = st[j + e]; }
                y1[e] = to_tf32((a1[e] * c - a2[e] * s) * 0.125f);
                y2[e] = to_tf32((a2[e] * c + a1[e] * s) * 0.125f);
            }
            uint32_t o0 = QS_OFF + sw128((uint32_t)(row * 128 + j * 4));
            uint32_t o1 = QS_OFF + 16384u + sw128((uint32_t)(row * 128 + j * 4));
            *(float4*)(sm + o0) = make_float4(y1[0], y1[1], y1[2], y1[3]);
            *(float4*)(sm + o1) = make_float4(y2[0], y2[1], y2[2], y2[3]);
        }
    }

#pragma unroll
    for (int u = tid; u < 512; u += 256) {
        int row = u >> 1, part = u & 1;
        const float* src = Kg + ((size_t)(b * LKV_ + row) * KVH_ + kvh) * HD_;
        int pos = rope ? (row / kdiv) : 0;
        const float* ct = g_rope + pos * 32;
        const float* st = g_rope + NF_MAX * 32 + pos * 32;
#pragma unroll
        for (int jj = 0; jj < 4; jj++) {
            int j = part * 16 + jj * 4;
            float4 x1 = *(const float4*)(src + j);
            float4 x2 = *(const float4*)(src + j + 32);
            float a1[4] = {x1.x, x1.y, x1.z, x1.w};
            float a2[4] = {x2.x, x2.y, x2.z, x2.w};
            float y1[4], y2[4];
#pragma unroll
            for (int e = 0; e < 4; e++) {
                float c = 1.f, s = 0.f;
                if (rope) { c = ct[j + e]; s = st[j + e]; }
                y1[e] = to_tf32(a1[e] * c - a2[e] * s);
                y2[e] = to_tf32(a2[e] * c + a1[e] * s);
            }
            uint32_t o0 = KS_OFF + sw128((uint32_t)(row * 128 + j * 4));
            uint32_t o1 = KS_OFF + 32768u + sw128((uint32_t)(row * 128 + j * 4));
            *(float4*)(sm + o0) = make_float4(y1[0], y1[1], y1[2], y1[3]);
            *(float4*)(sm + o1) = make_float4(y2[0], y2[1], y2[2], y2[3]);
        }
    }

#pragma unroll
    for (int i = 0; i < 16; i++) {
        int kv = w * 32 + (l & 15) + ((i & 1) << 4);
        int d4 = (l >> 4) + ((i >> 1) << 1);
        const float* src = Vg + ((size_t)(b * LKV_ + kv) * KVH_ + kvh) * HD_ + d4 * 4;
        float4 v = *(const float4*)src;
        float a[4] = {to_tf32(v.x), to_tf32(v.y), to_tf32(v.z), to_tf32(v.w)};
        uint32_t base = VT_OFF + (uint32_t)(kv >> 5) * 8192u;
#pragma unroll
        for (int c = 0; c < 4; c++) {
            int d = 4 * d4 + c;
            *(float*)(sm + base + sw128((uint32_t)(d * 128 + (kv & 31) * 4))) = a[c];
        }
    }
    __syncthreads();

    int lmat = l >> 3, lrow = l & 7;
    int frow = ((lmat & 2) ? 8 : 0) + lrow;
    int fcol = (lmat & 1) * 16;
    int mrow = w * 16 + frow;

    uint32_t qf[8][4];
#pragma unroll
    for (int kk = 0; kk < 8; kk++) {
        uint32_t a = smb + QS_OFF + (uint32_t)(kk >> 2) * 16384u
                   + sw128((uint32_t)(mrow * 128 + (kk & 3) * 32 + fcol));
        LDSM4(qf[kk], a);
    }

    float oacc[8][4];
#pragma unroll
    for (int i = 0; i < 8; i++)
#pragma unroll
        for (int j = 0; j < 4; j++) oacc[i][j] = 0.f;
    float rs0 = 0.f, rs1 = 0.f;

#pragma unroll
    for (int c = 0; c < 2; c++) {
        float sc[16][4];
#pragma unroll
        for (int i = 0; i < 16; i++)
#pragma unroll
            for (int j = 0; j < 4; j++) sc[i][j] = 0.f;

#pragma unroll
        for (int ng = 0; ng < 8; ng++) {
            int kvrow = c * 128 + ng * 16 + frow;
#pragma unroll
            for (int kk = 0; kk < 8; kk++) {
                uint32_t bf[4];
                uint32_t a = smb + KS_OFF + (uint32_t)(kk >> 2) * 32768u
                           + sw128((uint32_t)(kvrow * 128 + (kk & 3) * 32 + fcol));
                LDSM4(bf, a);
                MMA_TF32(sc[2 * ng],     qf[kk][0], qf[kk][2], qf[kk][1], qf[kk][3], bf[0], bf[1]);
                MMA_TF32(sc[2 * ng + 1], qf[kk][0], qf[kk][2], qf[kk][1], qf[kk][3], bf[2], bf[3]);
            }
        }

        int r0 = w * 16 + (l >> 2);
#pragma unroll
        for (int nt = 0; nt < 16; nt++) {
            float p0 = __expf(sc[nt][0]);
            float p1 = __expf(sc[nt][1]);
            float p2 = __expf(sc[nt][2]);
            float p3 = __expf(sc[nt][3]);
            rs0 += p0 + p1;
            rs1 += p2 + p3;
            int kvl = nt * 8 + 2 * (l & 3);
            uint32_t bo = PS_OFF + (uint32_t)(kvl >> 5) * 16384u;
            *(float2*)(sm + bo + sw128((uint32_t)(r0 * 128 + (kvl & 31) * 4)))
                = make_float2(to_tf32(p0), to_tf32(p1));
            *(float2*)(sm + bo + sw128((uint32_t)((r0 + 8) * 128 + (kvl & 31) * 4)))
                = make_float2(to_tf32(p2), to_tf32(p3));
        }
        __syncwarp();

        uint32_t pf[16][4];
#pragma unroll
        for (int kt = 0; kt < 16; kt++) {
            uint32_t a = smb + PS_OFF + (uint32_t)(kt >> 2) * 16384u
                       + sw128((uint32_t)(mrow * 128 + (kt & 3) * 32 + fcol));
            LDSM4(pf[kt], a);
        }
#pragma unroll
        for (int dg = 0; dg < 4; dg++) {
#pragma unroll
            for (int kt = 0; kt < 16; kt++) {
                uint32_t bf[4];
                uint32_t a = smb + VT_OFF + (uint32_t)(c * 4 + (kt >> 2)) * 8192u
                           + sw128((uint32_t)((dg * 16 + frow) * 128 + (kt & 3) * 32 + fcol));
                LDSM4(bf, a);
                MMA_TF32(oacc[2 * dg],     pf[kt][0], pf[kt][2], pf[kt][1], pf[kt][3], bf[0], bf[1]);
                MMA_TF32(oacc[2 * dg + 1], pf[kt][0], pf[kt][2], pf[kt][1], pf[kt][3], bf[2], bf[3]);
            }
        }
        __syncwarp();
    }

    rs0 += __shfl_xor_sync(0xFFFFFFFFu, rs0, 1);
    rs0 += __shfl_xor_sync(0xFFFFFFFFu, rs0, 2);
    rs1 += __shfl_xor_sync(0xFFFFFFFFu, rs1, 1);
    rs1 += __shfl_xor_sync(0xFFFFFFFFu, rs1, 2);
    float inv0 = 1.0f / rs0, inv1 = 1.0f / rs1;

    int q0 = qt * 128 + w * 16 + (l >> 2);
    float* o0 = O + ((size_t)(b * LQ_ + q0)) * D_ + h * HD_;
    float* o1 = o0 + 8 * D_;
#pragma unroll
    for (int nt = 0; nt < 8; nt++) {
        int dcol = nt * 8 + 2 * (l & 3);
        *(float2*)(o0 + dcol) = make_float2(to_tf32(oacc[nt][0] * inv0),
                                            to_tf32(oacc[nt][1] * inv0));
        *(float2*)(o1 + dcol) = make_float2(to_tf32(oacc[nt][2] * inv1),
                                            to_tf32(oacc[nt][3] * inv1));
    }
}

// ---------------------------------------------------------------------------
extern "C" void kernel_launch(void* const* d_in, const int* in_sizes, int n_in,
                              void* d_out, int out_size)
{
    const float* patches = (const float*)d_in[0];
    const float* latents = (const float*)d_in[1];
    const float* Wq = (const float*)d_in[2];
    const float* bq = (const float*)d_in[3];
    const float* Wk = (const float*)d_in[4];
    const float* bk = (const float*)d_in[5];
    const float* Wv = (const float*)d_in[6];
    const float* bv = (const float*)d_in[7];
    const float* Wo = (const float*)d_in[8];
    const float* bo = (const float*)d_in[9];
    const int*   nf = (const int*)d_in[10];
    float* out = (float*)d_out;

    float *Pd, *Ld, *Qd, *Kd, *Vd, *Ad, *WtQ, *WtK, *WtV, *WtO;
    cudaGetSymbolAddress((void**)&Pd,  g_P);
    cudaGetSymbolAddress((void**)&Ld,  g_L);
    cudaGetSymbolAddress((void**)&Qd,  g_Q);
    cudaGetSymbolAddress((void**)&Kd,  g_K);
    cudaGetSymbolAddress((void**)&Vd,  g_V);
    cudaGetSymbolAddress((void**)&Ad,  g_attn);
    cudaGetSymbolAddress((void**)&WtQ, g_WtQ);
    cudaGetSymbolAddress((void**)&WtK, g_WtK);
    cudaGetSymbolAddress((void**)&WtV, g_WtV);
    cudaGetSymbolAddress((void**)&WtO, g_WtO);

    cudaFuncSetAttribute(gemm_tf32, cudaFuncAttributeMaxDynamicSharedMemorySize, GEMM_SMEM);
    cudaFuncSetAttribute(attn_kernel, cudaFuncAttributeMaxDynamicSharedMemorySize, ATTN_SMEM);

    // 0) prep
    dim3 tb(32, 8);
    transpose_kernel<<<dim3(D_ / 32, D_ / 32), tb>>>(Wq, WtQ, D_, D_);
    transpose_kernel<<<dim3((KVH_ * HD_) / 32, D_ / 32), tb>>>(Wk, WtK, D_, KVH_ * HD_);
    transpose_kernel<<<dim3((KVH_ * HD_) / 32, D_ / 32), tb>>>(Wv, WtV, D_, KVH_ * HD_);
    transpose_kernel<<<dim3(D_ / 32, D_ / 32), tb>>>(Wo, WtO, D_, D_);
    rope_table_kernel<<<(NF_MAX * 32) / 256, 256>>>(nf);
    int np4 = B_ * LQ_ * D_ / 4;
    cvt_tf32_kernel<<<(np4 + 255) / 256, 256>>>(patches, Pd, np4);
    int nl4 = B_ * LKV_ * D_ / 4;
    cvt_tf32_kernel<<<(nl4 + 255) / 256, 256>>>(latents, Ld, nl4);

    // 1) Q projection
    gemm_tf32<<<dim3(D_ / 256, (B_ * LQ_) / 128), 256, GEMM_SMEM>>>(
        Pd, WtQ, bq, Qd, B_ * LQ_, D_, D_);

    // 2) K / V projections
    gemm_tf32<<<dim3((KVH_ * HD_) / 256, (B_ * LKV_) / 128), 256, GEMM_SMEM>>>(
        Ld, WtK, bk, Kd, B_ * LKV_, KVH_ * HD_, D_);
    gemm_tf32<<<dim3((KVH_ * HD_) / 256, (B_ * LKV_) / 128), 256, GEMM_SMEM>>>(
        Ld, WtV, bv, Vd, B_ * LKV_, KVH_ * HD_, D_);

    // 3) attention (mma + fused RoPE) -> tf32-rounded g_attn
    dim3 ga(LQ_ / 128, H_, B_);
    attn_kernel<<<ga, 256, ATTN_SMEM>>>(Qd, Kd, Vd, Ad, nf);

    // 4) output projection
    gemm_tf32<<<dim3(D_ / 256, (B_ * LQ_) / 128), 256, GEMM_SMEM>>>(
        Ad, WtO, bo, out, B_ * LQ_, D_, D_);
}

// round 6
// speedup vs baseline: 1.2229x; 1.2229x over previous
#include <cuda_runtime.h>
#include <math.h>
#include <stdint.h>

#define B_    4
#define LQ_   4096
#define LKV_  256
#define D_    1024
#define H_    16
#define KVH_  4
#define HD_   64
#define NF_MAX 4096

// ---------------- scratch (device globals; no allocation allowed) ----------
__device__ float g_Q[(size_t)B_ * LQ_ * D_];
__device__ float g_K[(size_t)B_ * LKV_ * KVH_ * HD_];
__device__ float g_V[(size_t)B_ * LKV_ * KVH_ * HD_];
__device__ float g_attn[(size_t)B_ * LQ_ * D_];         // tf32-rounded attn out
__device__ float g_WtQ[(size_t)D_ * D_];                // W^T [N][K], tf32-rounded
__device__ float g_WtK[(size_t)(KVH_ * HD_) * D_];
__device__ float g_WtV[(size_t)(KVH_ * HD_) * D_];
__device__ float g_WtO[(size_t)D_ * D_];
__device__ float g_rope[2 * NF_MAX * 32];               // cos | sin

// ---------------- helpers ---------------------------------------------------
__device__ __forceinline__ uint32_t smem_u32(const void* p) {
    uint32_t a;
    asm("{ .reg .u64 t; cvta.to.shared.u64 t, %1; cvt.u32.u64 %0, t; }"
        : "=r"(a) : "l"(p));
    return a;
}
__device__ __forceinline__ uint32_t sw128(uint32_t off) {
    return off ^ ((off >> 3) & 0x70);
}
__device__ __forceinline__ float to_tf32(float x) {
    uint32_t u;
    asm("cvt.rna.tf32.f32 %0, %1;" : "=r"(u) : "f"(x));
    return __uint_as_float(u);
}
// round raw fp32 bits held in a u32 reg to tf32 (in place)
#define CVT_FRAG(x) \
    asm("cvt.rna.tf32.f32 %0, %1;" : "=r"(x) : "f"(__uint_as_float(x)))

#define CP_A16(d, s) \
    asm volatile("cp.async.cg.shared.global [%0], [%1], 16;" :: "r"(d), "l"(s) : "memory")
#define CP_COMMIT() asm volatile("cp.async.commit_group;" ::: "memory")
#define CP_WAIT1()  asm volatile("cp.async.wait_group 1;" ::: "memory")
#define CP_WAIT0()  asm volatile("cp.async.wait_group 0;" ::: "memory")
#define LDSM4(r, addr) \
    asm volatile("ldmatrix.sync.aligned.m8n8.x4.shared.b16 {%0,%1,%2,%3}, [%4];" \
        : "=r"((r)[0]), "=r"((r)[1]), "=r"((r)[2]), "=r"((r)[3]) : "r"(addr))
#define MMA_TF32(d, a0, a1, a2, a3, b0, b1) \
    asm volatile("mma.sync.aligned.m16n8k8.row.col.f32.tf32.tf32.f32 " \
        "{%0,%1,%2,%3}, {%4,%5,%6,%7}, {%8,%9}, {%0,%1,%2,%3};" \
        : "+f"((d)[0]), "+f"((d)[1]), "+f"((d)[2]), "+f"((d)[3]) \
        : "r"(a0), "r"(a1), "r"(a2), "r"(a3), "r"(b0), "r"(b1))

// ---------------------------------------------------------------------------
__global__ void transpose_kernel(const float* __restrict__ W, float* __restrict__ Wt,
                                 int K, int N)
{
    __shared__ float t[32][33];
    int nb = blockIdx.x * 32, kb = blockIdx.y * 32;
    int x = threadIdx.x, y = threadIdx.y;   // 32 x 8
#pragma unroll
    for (int i = 0; i < 32; i += 8)
        t[y + i][x] = W[(size_t)(kb + y + i) * N + nb + x];
    __syncthreads();
#pragma unroll
    for (int i = 0; i < 32; i += 8)
        Wt[(size_t)(nb + y + i) * K + kb + x] = to_tf32(t[x][y + i]);
}

__global__ void rope_table_kernel(const int* __restrict__ nf_ptr)
{
    int nf = *nf_ptr;
    if (nf <= 1 || nf > NF_MAX) return;
    int idx = blockIdx.x * blockDim.x + threadIdx.x;
    if (idx >= nf * 32) return;
    int j = idx & 31, pos = idx >> 5;
    float inv = powf(10000.0f, -(float)(2 * j) / 64.0f);
    float th = (float)pos * inv;
    g_rope[idx] = cosf(th);
    g_rope[NF_MAX * 32 + idx] = sinf(th);
}

// ---------------------------------------------------------------------------
// tf32 mma.sync GEMM: C[M,N] = A[M,K] @ Bt[N,K]^T + bias
// CTA tile 128x128, 128 threads (4 warps, warp tile 64x64), BK=32,
// 2-stage cp.async. A is raw fp32 (tf32-rounded in fragments); Bt pre-rounded.
// grid(N/128, M/128).
// ---------------------------------------------------------------------------
#define GEMM_SMEM (1024 + 4 * 16384)

__device__ __forceinline__ void load_tile(const float* Ag, const float* Bg, int K,
                                          uint32_t aBuf, uint32_t bBuf, int tid)
{
#pragma unroll
    for (int j = 0; j < 8; j++) {
        int idx = j * 128 + tid;
        int row = idx >> 3, k4 = idx & 7;
        uint32_t off = sw128((uint32_t)(row * 128 + k4 * 16));
        CP_A16(aBuf + off, Ag + (size_t)row * K + k4 * 4);
        CP_A16(bBuf + off, Bg + (size_t)row * K + k4 * 4);
    }
}

__global__ __launch_bounds__(128)
void gemm_tf32(const float* __restrict__ A, const float* __restrict__ Bt,
               const float* __restrict__ bias, float* __restrict__ C,
               int M, int N, int K)
{
    extern __shared__ char smraw[];
    uint32_t base = smem_u32(smraw);
    uint32_t data = (base + 1023u) & ~1023u;

    int tid = threadIdx.x, lane = tid & 31, wid = tid >> 5;
    int wm = (wid >> 1) * 64;   // 2 warp rows
    int wn = (wid & 1) * 64;    // 2 warp cols

    const float* Ag = A  + (size_t)blockIdx.y * 128 * K;
    const float* Bg = Bt + (size_t)blockIdx.x * 128 * K;

    float acc[4][8][4];
#pragma unroll
    for (int i = 0; i < 4; i++)
#pragma unroll
        for (int j = 0; j < 8; j++)
#pragma unroll
            for (int k = 0; k < 4; k++) acc[i][j][k] = 0.f;

    int T = K >> 5;
    load_tile(Ag, Bg, K, data, data + 16384u, tid);
    CP_COMMIT();

    int lmat = lane >> 3, lrow = lane & 7;
    int frow = ((lmat & 2) ? 8 : 0) + lrow;
    int fcol = (lmat & 1) * 16;

    for (int t = 0; t < T; ++t) {
        int st = t & 1;
        if (t + 1 < T) {
            uint32_t nb = data + (uint32_t)((t + 1) & 1) * 32768u;
            load_tile(Ag + (t + 1) * 32, Bg + (t + 1) * 32, K, nb, nb + 16384u, tid);
            CP_COMMIT();
            CP_WAIT1();
        } else {
            CP_WAIT0();
        }
        __syncthreads();

        uint32_t aB = data + (uint32_t)st * 32768u;
        uint32_t bB = aB + 16384u;
#pragma unroll
        for (int kk = 0; kk < 4; ++kk) {
            uint32_t af[4][4], bf[4][4];
#pragma unroll
            for (int mi = 0; mi < 4; ++mi) {
                uint32_t addr = aB + sw128((uint32_t)((wm + mi * 16 + frow) * 128 + kk * 32 + fcol));
                LDSM4(af[mi], addr);
                CVT_FRAG(af[mi][0]); CVT_FRAG(af[mi][1]);
                CVT_FRAG(af[mi][2]); CVT_FRAG(af[mi][3]);
            }
#pragma unroll
            for (int nj = 0; nj < 4; ++nj) {
                uint32_t addr = bB + sw128((uint32_t)((wn + nj * 16 + frow) * 128 + kk * 32 + fcol));
                LDSM4(bf[nj], addr);
            }
#pragma unroll
            for (int mi = 0; mi < 4; ++mi)
#pragma unroll
                for (int ni = 0; ni < 8; ++ni) {
                    int nj = ni >> 1, lh = (ni & 1) * 2;
                    MMA_TF32(acc[mi][ni],
                             af[mi][0], af[mi][2], af[mi][1], af[mi][3],
                             bf[nj][lh], bf[nj][lh + 1]);
                }
        }
        __syncthreads();
    }

    int rbase = blockIdx.y * 128 + wm + (lane >> 2);
    int cbase = blockIdx.x * 128 + wn + (lane & 3) * 2;
#pragma unroll
    for (int mi = 0; mi < 4; ++mi) {
#pragma unroll
        for (int ni = 0; ni < 8; ++ni) {
            int c = cbase + ni * 8;
            float2 bv = *(const float2*)(bias + c);
            int r0 = rbase + mi * 16;
            float2 v0 = { acc[mi][ni][0] + bv.x, acc[mi][ni][1] + bv.y };
            *(float2*)(C + (size_t)r0 * N + c) = v0;
            float2 v1 = { acc[mi][ni][2] + bv.x, acc[mi][ni][3] + bv.y };
            *(float2*)(C + (size_t)(r0 + 8) * N + c) = v1;
        }
    }
}

// ---------------------------------------------------------------------------
// MMA flash attention with fused RoPE (unchanged from round 4).
// ---------------------------------------------------------------------------
#define QS_OFF 0u
#define KS_OFF 32768u
#define VT_OFF 98304u
#define PS_OFF 163840u
#define ATTN_SMEM 229376

__global__ __launch_bounds__(256, 1)
void attn_kernel(const float* __restrict__ Q, const float* __restrict__ Kg,
                 const float* __restrict__ Vg, float* __restrict__ O,
                 const int* __restrict__ nf_ptr)
{
    extern __shared__ char sm[];
    uint32_t smb = smem_u32(sm);

    int tid = threadIdx.x, l = tid & 31, w = tid >> 5;
    int b = blockIdx.z, h = blockIdx.y, qt = blockIdx.x;
    int kvh = h >> 2;
    int nf = *nf_ptr;
    bool rope = (nf > 1) && (nf <= NF_MAX);
    int qdiv = rope ? (LQ_ / nf) : 1;
    int kdiv = rope ? (LKV_ / nf) : 1;

    {
        int row = tid >> 1, part = tid & 1;
        int qglob = qt * 128 + row;
        const float* src = Q + ((size_t)(b * LQ_ + qglob)) * D_ + h * HD_;
        int pos = rope ? (qglob / qdiv) : 0;
        const float* ct = g_rope + pos * 32;
        const float* st = g_rope + NF_MAX * 32 + pos * 32;
#pragma unroll
        for (int jj = 0; jj < 4; jj++) {
            int j = part * 16 + jj * 4;
            float4 x1 = *(const float4*)(src + j);
            float4 x2 = *(const float4*)(src + j + 32);
            float y1[4], y2[4];
            float a1[4] = {x1.x, x1.y, x1.z, x1.w};
            float a2[4] = {x2.x, x2.y, x2.z, x2.w};
#pragma unroll
            for (int e = 0; e < 4; e++) {
                float c = 1.f, s = 0.f;
                if (rope) { c = ct[j + e]; s = st[j + e]; }
                y1[e] = to_tf32((a1[e] * c - a2[e] * s) * 0.125f);
                y2[e] = to_tf32((a2[e] * c + a1[e] * s) * 0.125f);
            }
            uint32_t o0 = QS_OFF + sw128((uint32_t)(row * 128 + j * 4));
            uint32_t o1 = QS_OFF + 16384u + sw128((uint32_t)(row * 128 + j * 4));
            *(float4*)(sm + o0) = make_float4(y1[0], y1[1], y1[2], y1[3]);
            *(float4*)(sm + o1) = make_float4(y2[0], y2[1], y2[2], y2[3]);
        }
    }

#pragma unroll
    for (int u = tid; u < 512; u += 256) {
        int row = u >> 1, part = u & 1;
        const float* src = Kg + ((size_t)(b * LKV_ + row) * KVH_ + kvh) * HD_;
        int pos = rope ? (row / kdiv) : 0;
        const float* ct = g_rope + pos * 32;
        const float* st = g_rope + NF_MAX * 32 + pos * 32;
#pragma unroll
        for (int jj = 0; jj < 4; jj++) {
            int j = part * 16 + jj * 4;
            float4 x1 = *(const float4*)(src + j);
            float4 x2 = *(const float4*)(src + j + 32);
            float a1[4] = {x1.x, x1.y, x1.z, x1.w};
            float a2[4] = {x2.x, x2.y, x2.z, x2.w};
            float y1[4], y2[4];
#pragma unroll
            for (int e = 0; e < 4; e++) {
                float c = 1.f, s = 0.f;
                if (rope) { c = ct[j + e]; s = st[j + e]; }
                y1[e] = to_tf32(a1[e] * c - a2[e] * s);
                y2[e] = to_tf32(a2[e] * c + a1[e] * s);
            }
            uint32_t o0 = KS_OFF + sw128((uint32_t)(row * 128 + j * 4));
            uint32_t o1 = KS_OFF + 32768u + sw128((uint32_t)(row * 128 + j * 4));
            *(float4*)(sm + o0) = make_float4(y1[0], y1[1], y1[2], y1[3]);
            *(float4*)(sm + o1) = make_float4(y2[0], y2[1], y2[2], y2[3]);
        }
    }

#pragma unroll
    for (int i = 0; i < 16; i++) {
        int kv = w * 32 + (l & 15) + ((i & 1) << 4);
        int d4 = (l >> 4) + ((i >> 1) << 1);
        const float* src = Vg + ((size_t)(b * LKV_ + kv) * KVH_ + kvh) * HD_ + d4 * 4;
        float4 v = *(const float4*)src;
        float a[4] = {to_tf32(v.x), to_tf32(v.y), to_tf32(v.z), to_tf32(v.w)};
        uint32_t base = VT_OFF + (uint32_t)(kv >> 5) * 8192u;
#pragma unroll
        for (int c = 0; c < 4; c++) {
            int d = 4 * d4 + c;
            *(float*)(sm + base + sw128((uint32_t)(d * 128 + (kv & 31) * 4))) = a[c];
        }
    }
    __syncthreads();

    int lmat = l >> 3, lrow = l & 7;
    int frow = ((lmat & 2) ? 8 : 0) + lrow;
    int fcol = (lmat & 1) * 16;
    int mrow = w * 16 + frow;

    uint32_t qf[8][4];
#pragma unroll
    for (int kk = 0; kk < 8; kk++) {
        uint32_t a = smb + QS_OFF + (uint32_t)(kk >> 2) * 16384u
                   + sw128((uint32_t)(mrow * 128 + (kk & 3) * 32 + fcol));
        LDSM4(qf[kk], a);
    }

    float oacc[8][4];
#pragma unroll
    for (int i = 0; i < 8; i++)
#pragma unroll
        for (int j = 0; j < 4; j++) oacc[i][j] = 0.f;
    float rs0 = 0.f, rs1 = 0.f;

#pragma unroll
    for (int c = 0; c < 2; c++) {
        float sc[16][4];
#pragma unroll
        for (int i = 0; i < 16; i++)
#pragma unroll
            for (int j = 0; j < 4; j++) sc[i][j] = 0.f;

#pragma unroll
        for (int ng = 0; ng < 8; ng++) {
            int kvrow = c * 128 + ng * 16 + frow;
#pragma unroll
            for (int kk = 0; kk < 8; kk++) {
                uint32_t bf[4];
                uint32_t a = smb + KS_OFF + (uint32_t)(kk >> 2) * 32768u
                           + sw128((uint32_t)(kvrow * 128 + (kk & 3) * 32 + fcol));
                LDSM4(bf, a);
                MMA_TF32(sc[2 * ng],     qf[kk][0], qf[kk][2], qf[kk][1], qf[kk][3], bf[0], bf[1]);
                MMA_TF32(sc[2 * ng + 1], qf[kk][0], qf[kk][2], qf[kk][1], qf[kk][3], bf[2], bf[3]);
            }
        }

        int r0 = w * 16 + (l >> 2);
#pragma unroll
        for (int nt = 0; nt < 16; nt++) {
            float p0 = __expf(sc[nt][0]);
            float p1 = __expf(sc[nt][1]);
            float p2 = __expf(sc[nt][2]);
            float p3 = __expf(sc[nt][3]);
            rs0 += p0 + p1;
            rs1 += p2 + p3;
            int kvl = nt * 8 + 2 * (l & 3);
            uint32_t bo = PS_OFF + (uint32_t)(kvl >> 5) * 16384u;
            *(float2*)(sm + bo + sw128((uint32_t)(r0 * 128 + (kvl & 31) * 4)))
                = make_float2(to_tf32(p0), to_tf32(p1));
            *(float2*)(sm + bo + sw128((uint32_t)((r0 + 8) * 128 + (kvl & 31) * 4)))
                = make_float2(to_tf32(p2), to_tf32(p3));
        }
        __syncwarp();

        uint32_t pf[16][4];
#pragma unroll
        for (int kt = 0; kt < 16; kt++) {
            uint32_t a = smb + PS_OFF + (uint32_t)(kt >> 2) * 16384u
                       + sw128((uint32_t)(mrow * 128 + (kt & 3) * 32 + fcol));
            LDSM4(pf[kt], a);
        }
#pragma unroll
        for (int dg = 0; dg < 4; dg++) {
#pragma unroll
            for (int kt = 0; kt < 16; kt++) {
                uint32_t bf[4];
                uint32_t a = smb + VT_OFF + (uint32_t)(c * 4 + (kt >> 2)) * 8192u
                           + sw128((uint32_t)((dg * 16 + frow) * 128 + (kt & 3) * 32 + fcol));
                LDSM4(bf, a);
                MMA_TF32(oacc[2 * dg],     pf[kt][0], pf[kt][2], pf[kt][1], pf[kt][3], bf[0], bf[1]);
                MMA_TF32(oacc[2 * dg + 1], pf[kt][0], pf[kt][2], pf[kt][1], pf[kt][3], bf[2], bf[3]);
            }
        }
        __syncwarp();
    }

    rs0 += __shfl_xor_sync(0xFFFFFFFFu, rs0, 1);
    rs0 += __shfl_xor_sync(0xFFFFFFFFu, rs0, 2);
    rs1 += __shfl_xor_sync(0xFFFFFFFFu, rs1, 1);
    rs1 += __shfl_xor_sync(0xFFFFFFFFu, rs1, 2);
    float inv0 = 1.0f / rs0, inv1 = 1.0f / rs1;

    int q0 = qt * 128 + w * 16 + (l >> 2);
    float* o0 = O + ((size_t)(b * LQ_ + q0)) * D_ + h * HD_;
    float* o1 = o0 + 8 * D_;
#pragma unroll
    for (int nt = 0; nt < 8; nt++) {
        int dcol = nt * 8 + 2 * (l & 3);
        *(float2*)(o0 + dcol) = make_float2(to_tf32(oacc[nt][0] * inv0),
                                            to_tf32(oacc[nt][1] * inv0));
        *(float2*)(o1 + dcol) = make_float2(to_tf32(oacc[nt][2] * inv1),
                                            to_tf32(oacc[nt][3] * inv1));
    }
}

// ---------------------------------------------------------------------------
extern "C" void kernel_launch(void* const* d_in, const int* in_sizes, int n_in,
                              void* d_out, int out_size)
{
    const float* patches = (const float*)d_in[0];
    const float* latents = (const float*)d_in[1];
    const float* Wq = (const float*)d_in[2];
    const float* bq = (const float*)d_in[3];
    const float* Wk = (const float*)d_in[4];
    const float* bk = (const float*)d_in[5];
    const float* Wv = (const float*)d_in[6];
    const float* bv = (const float*)d_in[7];
    const float* Wo = (const float*)d_in[8];
    const float* bo = (const float*)d_in[9];
    const int*   nf = (const int*)d_in[10];
    float* out = (float*)d_out;

    float *Qd, *Kd, *Vd, *Ad, *WtQ, *WtK, *WtV, *WtO;
    cudaGetSymbolAddress((void**)&Qd,  g_Q);
    cudaGetSymbolAddress((void**)&Kd,  g_K);
    cudaGetSymbolAddress((void**)&Vd,  g_V);
    cudaGetSymbolAddress((void**)&Ad,  g_attn);
    cudaGetSymbolAddress((void**)&WtQ, g_WtQ);
    cudaGetSymbolAddress((void**)&WtK, g_WtK);
    cudaGetSymbolAddress((void**)&WtV, g_WtV);
    cudaGetSymbolAddress((void**)&WtO, g_WtO);

    cudaFuncSetAttribute(gemm_tf32, cudaFuncAttributeMaxDynamicSharedMemorySize, GEMM_SMEM);
    cudaFuncSetAttribute(attn_kernel, cudaFuncAttributeMaxDynamicSharedMemorySize, ATTN_SMEM);

    // 0) prep: transposed tf32 weights + RoPE table
    dim3 tb(32, 8);
    transpose_kernel<<<dim3(D_ / 32, D_ / 32), tb>>>(Wq, WtQ, D_, D_);
    transpose_kernel<<<dim3((KVH_ * HD_) / 32, D_ / 32), tb>>>(Wk, WtK, D_, KVH_ * HD_);
    transpose_kernel<<<dim3((KVH_ * HD_) / 32, D_ / 32), tb>>>(Wv, WtV, D_, KVH_ * HD_);
    transpose_kernel<<<dim3(D_ / 32, D_ / 32), tb>>>(Wo, WtO, D_, D_);
    rope_table_kernel<<<(NF_MAX * 32) / 256, 256>>>(nf);

    // 1) Q projection (A = raw patches; tf32 cvt in fragments)
    gemm_tf32<<<dim3(D_ / 128, (B_ * LQ_) / 128), 128, GEMM_SMEM>>>(
        patches, WtQ, bq, Qd, B_ * LQ_, D_, D_);

    // 2) K / V projections
    gemm_tf32<<<dim3((KVH_ * HD_) / 128, (B_ * LKV_) / 128), 128, GEMM_SMEM>>>(
        latents, WtK, bk, Kd, B_ * LKV_, KVH_ * HD_, D_);
    gemm_tf32<<<dim3((KVH_ * HD_) / 128, (B_ * LKV_) / 128), 128, GEMM_SMEM>>>(
        latents, WtV, bv, Vd, B_ * LKV_, KVH_ * HD_, D_);

    // 3) attention (mma + fused RoPE) -> tf32-rounded g_attn
    dim3 ga(LQ_ / 128, H_, B_);
    attn_kernel<<<ga, 256, ATTN_SMEM>>>(Qd, Kd, Vd, Ad, nf);

    // 4) output projection
    gemm_tf32<<<dim3(D_ / 128, (B_ * LQ_) / 128), 128, GEMM_SMEM>>>(
        Ad, WtO, bo, out, B_ * LQ_, D_, D_);
}

// round 7
// speedup vs baseline: 1.9196x; 1.5698x over previous
#include <cuda_runtime.h>
#include <cuda_fp16.h>
#include <math.h>
#include <stdint.h>

#define B_    4
#define LQ_   4096
#define LKV_  256
#define D_    1024
#define H_    16
#define KVH_  4
#define HD_   64
#define NF_MAX 4096

// ---------------- scratch (device globals; no allocation allowed) ----------
__device__ __half g_Ph[(size_t)B_ * LQ_ * D_];          // fp16 patches
__device__ __half g_Lh[(size_t)B_ * LKV_ * D_];         // fp16 latents
__device__ float  g_Q[(size_t)B_ * LQ_ * D_];
__device__ float  g_K[(size_t)B_ * LKV_ * KVH_ * HD_];
__device__ float  g_V[(size_t)B_ * LKV_ * KVH_ * HD_];
__device__ __half g_attn[(size_t)B_ * LQ_ * D_];        // fp16 attn out
__device__ __half g_WtQ[(size_t)D_ * D_];               // W^T [N][K] fp16
__device__ __half g_WtK[(size_t)(KVH_ * HD_) * D_];
__device__ __half g_WtV[(size_t)(KVH_ * HD_) * D_];
__device__ __half g_WtO[(size_t)D_ * D_];
__device__ float  g_rope[2 * NF_MAX * 32];              // cos | sin

// ---------------- helpers ---------------------------------------------------
__device__ __forceinline__ uint32_t smem_u32(const void* p) {
    uint32_t a;
    asm("{ .reg .u64 t; cvta.to.shared.u64 t, %1; cvt.u32.u64 %0, t; }"
        : "=r"(a) : "l"(p));
    return a;
}
__device__ __forceinline__ uint32_t sw128(uint32_t off) {
    return off ^ ((off >> 3) & 0x70);
}
__device__ __forceinline__ float to_tf32(float x) {
    uint32_t u;
    asm("cvt.rna.tf32.f32 %0, %1;" : "=r"(u) : "f"(x));
    return __uint_as_float(u);
}

#define CP_A16(d, s) \
    asm volatile("cp.async.cg.shared.global [%0], [%1], 16;" :: "r"(d), "l"(s) : "memory")
#define CP_COMMIT() asm volatile("cp.async.commit_group;" ::: "memory")
#define CP_WAIT1()  asm volatile("cp.async.wait_group 1;" ::: "memory")
#define CP_WAIT0()  asm volatile("cp.async.wait_group 0;" ::: "memory")
#define LDSM4(r, addr) \
    asm volatile("ldmatrix.sync.aligned.m8n8.x4.shared.b16 {%0,%1,%2,%3}, [%4];" \
        : "=r"((r)[0]), "=r"((r)[1]), "=r"((r)[2]), "=r"((r)[3]) : "r"(addr))
#define MMA_TF32(d, a0, a1, a2, a3, b0, b1) \
    asm volatile("mma.sync.aligned.m16n8k8.row.col.f32.tf32.tf32.f32 " \
        "{%0,%1,%2,%3}, {%4,%5,%6,%7}, {%8,%9}, {%0,%1,%2,%3};" \
        : "+f"((d)[0]), "+f"((d)[1]), "+f"((d)[2]), "+f"((d)[3]) \
        : "r"(a0), "r"(a1), "r"(a2), "r"(a3), "r"(b0), "r"(b1))
#define MMA_F16(d, a0, a1, a2, a3, b0, b1) \
    asm volatile("mma.sync.aligned.m16n8k16.row.col.f32.f16.f16.f32 " \
        "{%0,%1,%2,%3}, {%4,%5,%6,%7}, {%8,%9}, {%0,%1,%2,%3};" \
        : "+f"((d)[0]), "+f"((d)[1]), "+f"((d)[2]), "+f"((d)[3]) \
        : "r"(a0), "r"(a1), "r"(a2), "r"(a3), "r"(b0), "r"(b1))

// ---------------------------------------------------------------------------
__global__ void cvt_f16_kernel(const float* __restrict__ in, __half* __restrict__ out, int n4)
{
    int i = blockIdx.x * blockDim.x + threadIdx.x;
    if (i >= n4) return;
    float4 v = reinterpret_cast<const float4*>(in)[i];
    __half2 h0 = __floats2half2_rn(v.x, v.y);
    __half2 h1 = __floats2half2_rn(v.z, v.w);
    reinterpret_cast<__half2*>(out)[2 * i]     = h0;
    reinterpret_cast<__half2*>(out)[2 * i + 1] = h1;
}

__global__ void transpose_kernel(const float* __restrict__ W, __half* __restrict__ Wt,
                                 int K, int N)
{
    __shared__ float t[32][33];
    int nb = blockIdx.x * 32, kb = blockIdx.y * 32;
    int x = threadIdx.x, y = threadIdx.y;   // 32 x 8
#pragma unroll
    for (int i = 0; i < 32; i += 8)
        t[y + i][x] = W[(size_t)(kb + y + i) * N + nb + x];
    __syncthreads();
#pragma unroll
    for (int i = 0; i < 32; i += 8)
        Wt[(size_t)(nb + y + i) * K + kb + x] = __float2half_rn(t[x][y + i]);
}

__global__ void rope_table_kernel(const int* __restrict__ nf_ptr)
{
    int nf = *nf_ptr;
    if (nf <= 1 || nf > NF_MAX) return;
    int idx = blockIdx.x * blockDim.x + threadIdx.x;
    if (idx >= nf * 32) return;
    int j = idx & 31, pos = idx >> 5;
    float inv = powf(10000.0f, -(float)(2 * j) / 64.0f);
    float th = (float)pos * inv;
    g_rope[idx] = cosf(th);
    g_rope[NF_MAX * 32 + idx] = sinf(th);
}

// ---------------------------------------------------------------------------
// fp16 mma.sync GEMM: C[M,N] = A[M,K] @ Bt[N,K]^T + bias (fp32 accum/out)
// CTA 128x128, 256 threads (8 warps, warp tile 64x32), BK=64 halves (128B row),
// 2-stage cp.async double buffer. grid(N/128, M/128).
// ---------------------------------------------------------------------------
#define GEMM_SMEM (1024 + 4 * 16384)

__device__ __forceinline__ void load_tile(const __half* Ag, const __half* Bg, int K,
                                          uint32_t aBuf, uint32_t bBuf, int tid)
{
#pragma unroll
    for (int j = 0; j < 4; j++) {
        int idx = j * 256 + tid;
        int row = idx >> 3, k8 = idx & 7;
        uint32_t off = sw128((uint32_t)(row * 128 + k8 * 16));
        CP_A16(aBuf + off, Ag + (size_t)row * K + k8 * 8);
        CP_A16(bBuf + off, Bg + (size_t)row * K + k8 * 8);
    }
}

__global__ __launch_bounds__(256)
void gemm_f16(const __half* __restrict__ A, const __half* __restrict__ Bt,
              const float* __restrict__ bias, float* __restrict__ C,
              int M, int N, int K)
{
    extern __shared__ char smraw[];
    uint32_t base = smem_u32(smraw);
    uint32_t data = (base + 1023u) & ~1023u;

    int tid = threadIdx.x, lane = tid & 31, wid = tid >> 5;
    int wm = (wid >> 2) * 64;   // 2 warp rows
    int wn = (wid & 3) * 32;    // 4 warp cols

    const __half* Ag = A  + (size_t)blockIdx.y * 128 * K;
    const __half* Bg = Bt + (size_t)blockIdx.x * 128 * K;

    float acc[4][4][4];
#pragma unroll
    for (int i = 0; i < 4; i++)
#pragma unroll
        for (int j = 0; j < 4; j++)
#pragma unroll
            for (int k = 0; k < 4; k++) acc[i][j][k] = 0.f;

    int T = K >> 6;   // BK = 64 halves
    load_tile(Ag, Bg, K, data, data + 16384u, tid);
    CP_COMMIT();

    int lmat = lane >> 3, lrow = lane & 7;
    int frow = ((lmat & 2) ? 8 : 0) + lrow;
    int fcol = (lmat & 1) * 16;   // byte offset: selects 16B (8-half) k-half

    for (int t = 0; t < T; ++t) {
        int st = t & 1;
        if (t + 1 < T) {
            uint32_t nb = data + (uint32_t)((t + 1) & 1) * 32768u;
            load_tile(Ag + (t + 1) * 64, Bg + (t + 1) * 64, K, nb, nb + 16384u, tid);
            CP_COMMIT();
            CP_WAIT1();
        } else {
            CP_WAIT0();
        }
        __syncthreads();

        uint32_t aB = data + (uint32_t)st * 32768u;
        uint32_t bB = aB + 16384u;
#pragma unroll
        for (int kk = 0; kk < 4; ++kk) {   // 4 x k16
            uint32_t af[4][4], bf[2][4];
#pragma unroll
            for (int mi = 0; mi < 4; ++mi) {
                uint32_t addr = aB + sw128((uint32_t)((wm + mi * 16 + frow) * 128 + kk * 32 + fcol));
                LDSM4(af[mi], addr);
            }
#pragma unroll
            for (int nj = 0; nj < 2; ++nj) {
                uint32_t addr = bB + sw128((uint32_t)((wn + nj * 16 + frow) * 128 + kk * 32 + fcol));
                LDSM4(bf[nj], addr);
            }
#pragma unroll
            for (int mi = 0; mi < 4; ++mi)
#pragma unroll
                for (int ni = 0; ni < 4; ++ni) {
                    int nj = ni >> 1, lh = (ni & 1) * 2;
                    MMA_F16(acc[mi][ni],
                            af[mi][0], af[mi][2], af[mi][1], af[mi][3],
                            bf[nj][lh], bf[nj][lh + 1]);
                }
        }
        __syncthreads();
    }

    int rbase = blockIdx.y * 128 + wm + (lane >> 2);
    int cbase = blockIdx.x * 128 + wn + (lane & 3) * 2;
#pragma unroll
    for (int mi = 0; mi < 4; ++mi) {
#pragma unroll
        for (int ni = 0; ni < 4; ++ni) {
            int c = cbase + ni * 8;
            float2 bv = *(const float2*)(bias + c);
            int r0 = rbase + mi * 16;
            float2 v0 = { acc[mi][ni][0] + bv.x, acc[mi][ni][1] + bv.y };
            *(float2*)(C + (size_t)r0 * N + c) = v0;
            float2 v1 = { acc[mi][ni][2] + bv.x, acc[mi][ni][3] + bv.y };
            *(float2*)(C + (size_t)(r0 + 8) * N + c) = v1;
        }
    }
}

// ---------------------------------------------------------------------------
// MMA flash attention with fused RoPE (round-4 proven internals; half output).
// ---------------------------------------------------------------------------
#define QS_OFF 0u
#define KS_OFF 32768u
#define VT_OFF 98304u
#define PS_OFF 163840u
#define ATTN_SMEM 229376

__global__ __launch_bounds__(256, 1)
void attn_kernel(const float* __restrict__ Q, const float* __restrict__ Kg,
                 const float* __restrict__ Vg, __half* __restrict__ O,
                 const int* __restrict__ nf_ptr)
{
    extern __shared__ char sm[];
    uint32_t smb = smem_u32(sm);

    int tid = threadIdx.x, l = tid & 31, w = tid >> 5;
    int b = blockIdx.z, h = blockIdx.y, qt = blockIdx.x;
    int kvh = h >> 2;
    int nf = *nf_ptr;
    bool rope = (nf > 1) && (nf <= NF_MAX);
    int qdiv = rope ? (LQ_ / nf) : 1;
    int kdiv = rope ? (LKV_ / nf) : 1;

    {
        int row = tid >> 1, part = tid & 1;
        int qglob = qt * 128 + row;
        const float* src = Q + ((size_t)(b * LQ_ + qglob)) * D_ + h * HD_;
        int pos = rope ? (qglob / qdiv) : 0;
        const float* ct = g_rope + pos * 32;
        const float* st = g_rope + NF_MAX * 32 + pos * 32;
#pragma unroll
        for (int jj = 0; jj < 4; jj++) {
            int j = part * 16 + jj * 4;
            float4 x1 = *(const float4*)(src + j);
            float4 x2 = *(const float4*)(src + j + 32);
            float y1[4], y2[4];
            float a1[4] = {x1.x, x1.y, x1.z, x1.w};
            float a2[4] = {x2.x, x2.y, x2.z, x2.w};
#pragma unroll
            for (int e = 0; e < 4; e++) {
                float c = 1.f, s = 0.f;
                if (rope) { c = ct[j + e]; s = st[j + e]; }
                y1[e] = to_tf32((a1[e] * c - a2[e] * s) * 0.125f);
                y2[e] = to_tf32((a2[e] * c + a1[e] * s) * 0.125f);
            }
            uint32_t o0 = QS_OFF + sw128((uint32_t)(row * 128 + j * 4));
            uint32_t o1 = QS_OFF + 16384u + sw128((uint32_t)(row * 128 + j * 4));
            *(float4*)(sm + o0) = make_float4(y1[0], y1[1], y1[2], y1[3]);
            *(float4*)(sm + o1) = make_float4(y2[0], y2[1], y2[2], y2[3]);
        }
    }

#pragma unroll
    for (int u = tid; u < 512; u += 256) {
        int row = u >> 1, part = u & 1;
        const float* src = Kg + ((size_t)(b * LKV_ + row) * KVH_ + kvh) * HD_;
        int pos = rope ? (row / kdiv) : 0;
        const float* ct = g_rope + pos * 32;
        const float* st = g_rope + NF_MAX * 32 + pos * 32;
#pragma unroll
        for (int jj = 0; jj < 4; jj++) {
            int j = part * 16 + jj * 4;
            float4 x1 = *(const float4*)(src + j);
            float4 x2 = *(const float4*)(src + j + 32);
            float a1[4] = {x1.x, x1.y, x1.z, x1.w};
            float a2[4] = {x2.x, x2.y, x2.z, x2.w};
            float y1[4], y2[4];
#pragma unroll
            for (int e = 0; e < 4; e++) {
                float c = 1.f, s = 0.f;
                if (rope) { c = ct[j + e]; s = st[j + e]; }
                y1[e] = to_tf32(a1[e] * c - a2[e] * s);
                y2[e] = to_tf32(a2[e] * c + a1[e] * s);
            }
            uint32_t o0 = KS_OFF + sw128((uint32_t)(row * 128 + j * 4));
            uint32_t o1 = KS_OFF + 32768u + sw128((uint32_t)(row * 128 + j * 4));
            *(float4*)(sm + o0) = make_float4(y1[0], y1[1], y1[2], y1[3]);
            *(float4*)(sm + o1) = make_float4(y2[0], y2[1], y2[2], y2[3]);
        }
    }

#pragma unroll
    for (int i = 0; i < 16; i++) {
        int kv = w * 32 + (l & 15) + ((i & 1) << 4);
        int d4 = (l >> 4) + ((i >> 1) << 1);
        const float* src = Vg + ((size_t)(b * LKV_ + kv) * KVH_ + kvh) * HD_ + d4 * 4;
        float4 v = *(const float4*)src;
        float a[4] = {to_tf32(v.x), to_tf32(v.y), to_tf32(v.z), to_tf32(v.w)};
        uint32_t base = VT_OFF + (uint32_t)(kv >> 5) * 8192u;
#pragma unroll
        for (int c = 0; c < 4; c++) {
            int d = 4 * d4 + c;
            *(float*)(sm + base + sw128((uint32_t)(d * 128 + (kv & 31) * 4))) = a[c];
        }
    }
    __syncthreads();

    int lmat = l >> 3, lrow = l & 7;
    int frow = ((lmat & 2) ? 8 : 0) + lrow;
    int fcol = (lmat & 1) * 16;
    int mrow = w * 16 + frow;

    uint32_t qf[8][4];
#pragma unroll
    for (int kk = 0; kk < 8; kk++) {
        uint32_t a = smb + QS_OFF + (uint32_t)(kk >> 2) * 16384u
                   + sw128((uint32_t)(mrow * 128 + (kk & 3) * 32 + fcol));
        LDSM4(qf[kk], a);
    }

    float oacc[8][4];
#pragma unroll
    for (int i = 0; i < 8; i++)
#pragma unroll
        for (int j = 0; j < 4; j++) oacc[i][j] = 0.f;
    float rs0 = 0.f, rs1 = 0.f;

#pragma unroll
    for (int c = 0; c < 2; c++) {
        float sc[16][4];
#pragma unroll
        for (int i = 0; i < 16; i++)
#pragma unroll
            for (int j = 0; j < 4; j++) sc[i][j] = 0.f;

#pragma unroll
        for (int ng = 0; ng < 8; ng++) {
            int kvrow = c * 128 + ng * 16 + frow;
#pragma unroll
            for (int kk = 0; kk < 8; kk++) {
                uint32_t bf[4];
                uint32_t a = smb + KS_OFF + (uint32_t)(kk >> 2) * 32768u
                           + sw128((uint32_t)(kvrow * 128 + (kk & 3) * 32 + fcol));
                LDSM4(bf, a);
                MMA_TF32(sc[2 * ng],     qf[kk][0], qf[kk][2], qf[kk][1], qf[kk][3], bf[0], bf[1]);
                MMA_TF32(sc[2 * ng + 1], qf[kk][0], qf[kk][2], qf[kk][1], qf[kk][3], bf[2], bf[3]);
            }
        }

        int r0 = w * 16 + (l >> 2);
#pragma unroll
        for (int nt = 0; nt < 16; nt++) {
            float p0 = __expf(sc[nt][0]);
            float p1 = __expf(sc[nt][1]);
            float p2 = __expf(sc[nt][2]);
            float p3 = __expf(sc[nt][3]);
            rs0 += p0 + p1;
            rs1 += p2 + p3;
            int kvl = nt * 8 + 2 * (l & 3);
            uint32_t bo = PS_OFF + (uint32_t)(kvl >> 5) * 16384u;
            *(float2*)(sm + bo + sw128((uint32_t)(r0 * 128 + (kvl & 31) * 4)))
                = make_float2(to_tf32(p0), to_tf32(p1));
            *(float2*)(sm + bo + sw128((uint32_t)((r0 + 8) * 128 + (kvl & 31) * 4)))
                = make_float2(to_tf32(p2), to_tf32(p3));
        }
        __syncwarp();

        uint32_t pf[16][4];
#pragma unroll
        for (int kt = 0; kt < 16; kt++) {
            uint32_t a = smb + PS_OFF + (uint32_t)(kt >> 2) * 16384u
                       + sw128((uint32_t)(mrow * 128 + (kt & 3) * 32 + fcol));
            LDSM4(pf[kt], a);
        }
#pragma unroll
        for (int dg = 0; dg < 4; dg++) {
#pragma unroll
            for (int kt = 0; kt < 16; kt++) {
                uint32_t bf[4];
                uint32_t a = smb + VT_OFF + (uint32_t)(c * 4 + (kt >> 2)) * 8192u
                           + sw128((uint32_t)((dg * 16 + frow) * 128 + (kt & 3) * 32 + fcol));
                LDSM4(bf, a);
                MMA_TF32(oacc[2 * dg],     pf[kt][0], pf[kt][2], pf[kt][1], pf[kt][3], bf[0], bf[1]);
                MMA_TF32(oacc[2 * dg + 1], pf[kt][0], pf[kt][2], pf[kt][1], pf[kt][3], bf[2], bf[3]);
            }
        }
        __syncwarp();
    }

    rs0 += __shfl_xor_sync(0xFFFFFFFFu, rs0, 1);
    rs0 += __shfl_xor_sync(0xFFFFFFFFu, rs0, 2);
    rs1 += __shfl_xor_sync(0xFFFFFFFFu, rs1, 1);
    rs1 += __shfl_xor_sync(0xFFFFFFFFu, rs1, 2);
    float inv0 = 1.0f / rs0, inv1 = 1.0f / rs1;

    int q0 = qt * 128 + w * 16 + (l >> 2);
    __half* o0 = O + ((size_t)(b * LQ_ + q0)) * D_ + h * HD_;
    __half* o1 = o0 + 8 * D_;
#pragma unroll
    for (int nt = 0; nt < 8; nt++) {
        int dcol = nt * 8 + 2 * (l & 3);
        *(__half2*)(o0 + dcol) = __floats2half2_rn(oacc[nt][0] * inv0, oacc[nt][1] * inv0);
        *(__half2*)(o1 + dcol) = __floats2half2_rn(oacc[nt][2] * inv1, oacc[nt][3] * inv1);
    }
}

// ---------------------------------------------------------------------------
extern "C" void kernel_launch(void* const* d_in, const int* in_sizes, int n_in,
                              void* d_out, int out_size)
{
    const float* patches = (const float*)d_in[0];
    const float* latents = (const float*)d_in[1];
    const float* Wq = (const float*)d_in[2];
    const float* bq = (const float*)d_in[3];
    const float* Wk = (const float*)d_in[4];
    const float* bk = (const float*)d_in[5];
    const float* Wv = (const float*)d_in[6];
    const float* bv = (const float*)d_in[7];
    const float* Wo = (const float*)d_in[8];
    const float* bo = (const float*)d_in[9];
    const int*   nf = (const int*)d_in[10];
    float* out = (float*)d_out;

    float *Qd, *Kd, *Vd;
    __half *Ph, *Lh, *Ad, *WtQ, *WtK, *WtV, *WtO;
    cudaGetSymbolAddress((void**)&Ph,  g_Ph);
    cudaGetSymbolAddress((void**)&Lh,  g_Lh);
    cudaGetSymbolAddress((void**)&Qd,  g_Q);
    cudaGetSymbolAddress((void**)&Kd,  g_K);
    cudaGetSymbolAddress((void**)&Vd,  g_V);
    cudaGetSymbolAddress((void**)&Ad,  g_attn);
    cudaGetSymbolAddress((void**)&WtQ, g_WtQ);
    cudaGetSymbolAddress((void**)&WtK, g_WtK);
    cudaGetSymbolAddress((void**)&WtV, g_WtV);
    cudaGetSymbolAddress((void**)&WtO, g_WtO);

    cudaFuncSetAttribute(gemm_f16, cudaFuncAttributeMaxDynamicSharedMemorySize, GEMM_SMEM);
    cudaFuncSetAttribute(attn_kernel, cudaFuncAttributeMaxDynamicSharedMemorySize, ATTN_SMEM);

    // 0) prep: fp16 transposed weights, fp16 activations, RoPE table
    dim3 tb(32, 8);
    transpose_kernel<<<dim3(D_ / 32, D_ / 32), tb>>>(Wq, WtQ, D_, D_);
    transpose_kernel<<<dim3((KVH_ * HD_) / 32, D_ / 32), tb>>>(Wk, WtK, D_, KVH_ * HD_);
    transpose_kernel<<<dim3((KVH_ * HD_) / 32, D_ / 32), tb>>>(Wv, WtV, D_, KVH_ * HD_);
    transpose_kernel<<<dim3(D_ / 32, D_ / 32), tb>>>(Wo, WtO, D_, D_);
    rope_table_kernel<<<(NF_MAX * 32) / 256, 256>>>(nf);
    int np4 = B_ * LQ_ * D_ / 4;
    cvt_f16_kernel<<<(np4 + 255) / 256, 256>>>(patches, Ph, np4);
    int nl4 = B_ * LKV_ * D_ / 4;
    cvt_f16_kernel<<<(nl4 + 255) / 256, 256>>>(latents, Lh, nl4);

    // 1) Q projection
    gemm_f16<<<dim3(D_ / 128, (B_ * LQ_) / 128), 256, GEMM_SMEM>>>(
        Ph, WtQ, bq, Qd, B_ * LQ_, D_, D_);

    // 2) K / V projections
    gemm_f16<<<dim3((KVH_ * HD_) / 128, (B_ * LKV_) / 128), 256, GEMM_SMEM>>>(
        Lh, WtK, bk, Kd, B_ * LKV_, KVH_ * HD_, D_);
    gemm_f16<<<dim3((KVH_ * HD_) / 128, (B_ * LKV_) / 128), 256, GEMM_SMEM>>>(
        Lh, WtV, bv, Vd, B_ * LKV_, KVH_ * HD_, D_);

    // 3) attention (tf32 mma + fused RoPE) -> fp16 g_attn
    dim3 ga(LQ_ / 128, H_, B_);
    attn_kernel<<<ga, 256, ATTN_SMEM>>>(Qd, Kd, Vd, Ad, nf);

    // 4) output projection
    gemm_f16<<<dim3(D_ / 128, (B_ * LQ_) / 128), 256, GEMM_SMEM>>>(
        Ad, WtO, bo, out, B_ * LQ_, D_, D_);
}

// round 8
// speedup vs baseline: 2.1630x; 1.1268x over previous
#include <cuda_runtime.h>
#include <cuda_fp16.h>
#include <math.h>
#include <stdint.h>

#define B_    4
#define LQ_   4096
#define LKV_  256
#define D_    1024
#define H_    16
#define KVH_  4
#define HD_   64
#define NF_MAX 4096

// ---------------- scratch (device globals; no allocation allowed) ----------
__device__ __half g_Ph[(size_t)B_ * LQ_ * D_];          // fp16 patches
__device__ __half g_Lh[(size_t)B_ * LKV_ * D_];         // fp16 latents
__device__ __half g_Q[(size_t)B_ * LQ_ * D_];           // fp16 Q
__device__ __half g_K[(size_t)B_ * LKV_ * KVH_ * HD_];
__device__ __half g_V[(size_t)B_ * LKV_ * KVH_ * HD_];
__device__ __half g_attn[(size_t)B_ * LQ_ * D_];        // fp16 attn out
__device__ __half g_WtQ[(size_t)D_ * D_];               // W^T [N][K] fp16
__device__ __half g_WtK[(size_t)(KVH_ * HD_) * D_];
__device__ __half g_WtV[(size_t)(KVH_ * HD_) * D_];
__device__ __half g_WtO[(size_t)D_ * D_];
__device__ float  g_rope[2 * NF_MAX * 32];              // cos | sin

// ---------------- helpers ---------------------------------------------------
__device__ __forceinline__ uint32_t smem_u32(const void* p) {
    uint32_t a;
    asm("{ .reg .u64 t; cvta.to.shared.u64 t, %1; cvt.u32.u64 %0, t; }"
        : "=r"(a) : "l"(p));
    return a;
}
__device__ __forceinline__ uint32_t sw128(uint32_t off) {
    return off ^ ((off >> 3) & 0x70);
}

#define CP_A16(d, s) \
    asm volatile("cp.async.cg.shared.global [%0], [%1], 16;" :: "r"(d), "l"(s) : "memory")
#define CP_COMMIT() asm volatile("cp.async.commit_group;" ::: "memory")
#define CP_WAIT1()  asm volatile("cp.async.wait_group 1;" ::: "memory")
#define CP_WAIT0()  asm volatile("cp.async.wait_group 0;" ::: "memory")
#define LDSM4(r, addr) \
    asm volatile("ldmatrix.sync.aligned.m8n8.x4.shared.b16 {%0,%1,%2,%3}, [%4];" \
        : "=r"((r)[0]), "=r"((r)[1]), "=r"((r)[2]), "=r"((r)[3]) : "r"(addr))
#define MMA_F16(d, a0, a1, a2, a3, b0, b1) \
    asm volatile("mma.sync.aligned.m16n8k16.row.col.f32.f16.f16.f32 " \
        "{%0,%1,%2,%3}, {%4,%5,%6,%7}, {%8,%9}, {%0,%1,%2,%3};" \
        : "+f"((d)[0]), "+f"((d)[1]), "+f"((d)[2]), "+f"((d)[3]) \
        : "r"(a0), "r"(a1), "r"(a2), "r"(a3), "r"(b0), "r"(b1))

__device__ __forceinline__ void store2(float* p, float x, float y) {
    *(float2*)p = make_float2(x, y);
}
__device__ __forceinline__ void store2(__half* p, float x, float y) {
    *(__half2*)p = __floats2half2_rn(x, y);
}

// ---------------------------------------------------------------------------
__global__ void cvt_f16_kernel(const float* __restrict__ in, __half* __restrict__ out, int n4)
{
    int i = blockIdx.x * blockDim.x + threadIdx.x;
    if (i >= n4) return;
    float4 v = reinterpret_cast<const float4*>(in)[i];
    reinterpret_cast<__half2*>(out)[2 * i]     = __floats2half2_rn(v.x, v.y);
    reinterpret_cast<__half2*>(out)[2 * i + 1] = __floats2half2_rn(v.z, v.w);
}

__global__ void transpose_kernel(const float* __restrict__ W, __half* __restrict__ Wt,
                                 int K, int N)
{
    __shared__ float t[32][33];
    int nb = blockIdx.x * 32, kb = blockIdx.y * 32;
    int x = threadIdx.x, y = threadIdx.y;   // 32 x 8
#pragma unroll
    for (int i = 0; i < 32; i += 8)
        t[y + i][x] = W[(size_t)(kb + y + i) * N + nb + x];
    __syncthreads();
#pragma unroll
    for (int i = 0; i < 32; i += 8)
        Wt[(size_t)(nb + y + i) * K + kb + x] = __float2half_rn(t[x][y + i]);
}

__global__ void rope_table_kernel(const int* __restrict__ nf_ptr)
{
    int nf = *nf_ptr;
    if (nf <= 1 || nf > NF_MAX) return;
    int idx = blockIdx.x * blockDim.x + threadIdx.x;
    if (idx >= nf * 32) return;
    int j = idx & 31, pos = idx >> 5;
    float inv = powf(10000.0f, -(float)(2 * j) / 64.0f);
    float th = (float)pos * inv;
    g_rope[idx] = cosf(th);
    g_rope[NF_MAX * 32 + idx] = sinf(th);
}

// ---------------------------------------------------------------------------
// fp16 mma.sync GEMM: C[M,N] = A[M,K] @ Bt[N,K]^T + bias (fp32 accum)
// CTA 128x128, 256 threads (8 warps, warp tile 64x32), BK=64 halves,
// 2-stage cp.async. Output type templated (float or __half).
// ---------------------------------------------------------------------------
#define GEMM_SMEM (1024 + 4 * 16384)

__device__ __forceinline__ void load_tile(const __half* Ag, const __half* Bg, int K,
                                          uint32_t aBuf, uint32_t bBuf, int tid)
{
#pragma unroll
    for (int j = 0; j < 4; j++) {
        int idx = j * 256 + tid;
        int row = idx >> 3, k8 = idx & 7;
        uint32_t off = sw128((uint32_t)(row * 128 + k8 * 16));
        CP_A16(aBuf + off, Ag + (size_t)row * K + k8 * 8);
        CP_A16(bBuf + off, Bg + (size_t)row * K + k8 * 8);
    }
}

template <typename OutT>
__global__ __launch_bounds__(256)
void gemm_f16(const __half* __restrict__ A, const __half* __restrict__ Bt,
              const float* __restrict__ bias, OutT* __restrict__ C,
              int M, int N, int K)
{
    extern __shared__ char smraw[];
    uint32_t base = smem_u32(smraw);
    uint32_t data = (base + 1023u) & ~1023u;

    int tid = threadIdx.x, lane = tid & 31, wid = tid >> 5;
    int wm = (wid >> 2) * 64;
    int wn = (wid & 3) * 32;

    const __half* Ag = A  + (size_t)blockIdx.y * 128 * K;
    const __half* Bg = Bt + (size_t)blockIdx.x * 128 * K;

    float acc[4][4][4];
#pragma unroll
    for (int i = 0; i < 4; i++)
#pragma unroll
        for (int j = 0; j < 4; j++)
#pragma unroll
            for (int k = 0; k < 4; k++) acc[i][j][k] = 0.f;

    int T = K >> 6;
    load_tile(Ag, Bg, K, data, data + 16384u, tid);
    CP_COMMIT();

    int lmat = lane >> 3, lrow = lane & 7;
    int frow = ((lmat & 2) ? 8 : 0) + lrow;
    int fcol = (lmat & 1) * 16;

    for (int t = 0; t < T; ++t) {
        int st = t & 1;
        if (t + 1 < T) {
            uint32_t nb = data + (uint32_t)((t + 1) & 1) * 32768u;
            load_tile(Ag + (t + 1) * 64, Bg + (t + 1) * 64, K, nb, nb + 16384u, tid);
            CP_COMMIT();
            CP_WAIT1();
        } else {
            CP_WAIT0();
        }
        __syncthreads();

        uint32_t aB = data + (uint32_t)st * 32768u;
        uint32_t bB = aB + 16384u;
#pragma unroll
        for (int kk = 0; kk < 4; ++kk) {
            uint32_t af[4][4], bf[2][4];
#pragma unroll
            for (int mi = 0; mi < 4; ++mi) {
                uint32_t addr = aB + sw128((uint32_t)((wm + mi * 16 + frow) * 128 + kk * 32 + fcol));
                LDSM4(af[mi], addr);
            }
#pragma unroll
            for (int nj = 0; nj < 2; ++nj) {
                uint32_t addr = bB + sw128((uint32_t)((wn + nj * 16 + frow) * 128 + kk * 32 + fcol));
                LDSM4(bf[nj], addr);
            }
#pragma unroll
            for (int mi = 0; mi < 4; ++mi)
#pragma unroll
                for (int ni = 0; ni < 4; ++ni) {
                    int nj = ni >> 1, lh = (ni & 1) * 2;
                    MMA_F16(acc[mi][ni],
                            af[mi][0], af[mi][2], af[mi][1], af[mi][3],
                            bf[nj][lh], bf[nj][lh + 1]);
                }
        }
        __syncthreads();
    }

    int rbase = blockIdx.y * 128 + wm + (lane >> 2);
    int cbase = blockIdx.x * 128 + wn + (lane & 3) * 2;
#pragma unroll
    for (int mi = 0; mi < 4; ++mi) {
#pragma unroll
        for (int ni = 0; ni < 4; ++ni) {
            int c = cbase + ni * 8;
            float2 bv = *(const float2*)(bias + c);
            int r0 = rbase + mi * 16;
            store2(C + (size_t)r0 * N + c, acc[mi][ni][0] + bv.x, acc[mi][ni][1] + bv.y);
            store2(C + (size_t)(r0 + 8) * N + c, acc[mi][ni][2] + bv.x, acc[mi][ni][3] + bv.y);
        }
    }
}

// ---------------------------------------------------------------------------
// fp16 MMA flash attention with fused RoPE. grid (LQ/128, H, B), 256 threads.
// SMEM (half, 128B swizzled rows of 64 halves):
//   QS 0      : [128][64] 16KB   (rope+scale)
//   KS 16384  : [256][64] 32KB   (rope)
//   VT 49152  : 4 x [64 d][64 kv] 32KB  (V transposed)
//   PS 81920  : 2 x [128][64] 32KB (P chunk scratch)
// ---------------------------------------------------------------------------
#define QS_OFF 0u
#define KS_OFF 16384u
#define VT_OFF 49152u
#define PS_OFF 81920u
#define ATTN_SMEM 114688

__global__ __launch_bounds__(256)
void attn_kernel(const __half* __restrict__ Q, const __half* __restrict__ Kg,
                 const __half* __restrict__ Vg, __half* __restrict__ O,
                 const int* __restrict__ nf_ptr)
{
    extern __shared__ char sm[];
    uint32_t smb = smem_u32(sm);

    int tid = threadIdx.x, l = tid & 31, w = tid >> 5;
    int b = blockIdx.z, h = blockIdx.y, qt = blockIdx.x;
    int kvh = h >> 2;
    int nf = *nf_ptr;
    bool rope = (nf > 1) && (nf <= NF_MAX);
    int qdiv = rope ? (LQ_ / nf) : 1;
    int kdiv = rope ? (LKV_ / nf) : 1;

    // ---- Q tile: rope + scale, half in/out ---------------------------------
    {
        int row = tid >> 1, part = tid & 1;
        int qglob = qt * 128 + row;
        const __half* src = Q + ((size_t)(b * LQ_ + qglob)) * D_ + h * HD_;
        int pos = rope ? (qglob / qdiv) : 0;
        const float* ct = g_rope + pos * 32;
        const float* st = g_rope + NF_MAX * 32 + pos * 32;
#pragma unroll
        for (int jj = 0; jj < 4; jj++) {
            int j = part * 16 + jj * 4;
            __half2 u0 = *(const __half2*)(src + j);
            __half2 u1 = *(const __half2*)(src + j + 2);
            __half2 v0 = *(const __half2*)(src + j + 32);
            __half2 v1 = *(const __half2*)(src + j + 34);
            float a1[4] = { __low2float(u0), __high2float(u0), __low2float(u1), __high2float(u1) };
            float a2[4] = { __low2float(v0), __high2float(v0), __low2float(v1), __high2float(v1) };
            float y1[4], y2[4];
#pragma unroll
            for (int e = 0; e < 4; e++) {
                float c = 1.f, s = 0.f;
                if (rope) { c = ct[j + e], s = st[j + e]; }
                y1[e] = (a1[e] * c - a2[e] * s) * 0.125f;
                y2[e] = (a2[e] * c + a1[e] * s) * 0.125f;
            }
            uint32_t o0 = QS_OFF + sw128((uint32_t)(row * 128 + j * 2));
            uint32_t o1 = QS_OFF + sw128((uint32_t)(row * 128 + (j + 32) * 2));
            ((__half2*)(sm + o0))[0] = __floats2half2_rn(y1[0], y1[1]);
            ((__half2*)(sm + o0))[1] = __floats2half2_rn(y1[2], y1[3]);
            ((__half2*)(sm + o1))[0] = __floats2half2_rn(y2[0], y2[1]);
            ((__half2*)(sm + o1))[1] = __floats2half2_rn(y2[2], y2[3]);
        }
    }

    // ---- K tile: rope -------------------------------------------------------
#pragma unroll
    for (int u = tid; u < 512; u += 256) {
        int row = u >> 1, part = u & 1;
        const __half* src = Kg + ((size_t)(b * LKV_ + row) * KVH_ + kvh) * HD_;
        int pos = rope ? (row / kdiv) : 0;
        const float* ct = g_rope + pos * 32;
        const float* st = g_rope + NF_MAX * 32 + pos * 32;
#pragma unroll
        for (int jj = 0; jj < 4; jj++) {
            int j = part * 16 + jj * 4;
            __half2 u0 = *(const __half2*)(src + j);
            __half2 u1 = *(const __half2*)(src + j + 2);
            __half2 v0 = *(const __half2*)(src + j + 32);
            __half2 v1 = *(const __half2*)(src + j + 34);
            float a1[4] = { __low2float(u0), __high2float(u0), __low2float(u1), __high2float(u1) };
            float a2[4] = { __low2float(v0), __high2float(v0), __low2float(v1), __high2float(v1) };
            float y1[4], y2[4];
#pragma unroll
            for (int e = 0; e < 4; e++) {
                float c = 1.f, s = 0.f;
                if (rope) { c = ct[j + e], s = st[j + e]; }
                y1[e] = a1[e] * c - a2[e] * s;
                y2[e] = a2[e] * c + a1[e] * s;
            }
            uint32_t o0 = KS_OFF + sw128((uint32_t)(row * 128 + j * 2));
            uint32_t o1 = KS_OFF + sw128((uint32_t)(row * 128 + (j + 32) * 2));
            ((__half2*)(sm + o0))[0] = __floats2half2_rn(y1[0], y1[1]);
            ((__half2*)(sm + o0))[1] = __floats2half2_rn(y1[2], y1[3]);
            ((__half2*)(sm + o1))[0] = __floats2half2_rn(y2[0], y2[1]);
            ((__half2*)(sm + o1))[1] = __floats2half2_rn(y2[2], y2[3]);
        }
    }

    // ---- V transposed: Vt[sub kv/64][d][kv%64] ------------------------------
#pragma unroll
    for (int it = 0; it < 8; it++) {
        int idx = it * 256 + tid;
        int kv = idx >> 3, c8 = idx & 7;       // 8 halves of d per chunk
        const __half* src = Vg + ((size_t)(b * LKV_ + kv) * KVH_ + kvh) * HD_ + c8 * 8;
        uint4 raw = *(const uint4*)src;
        const __half* hv = (const __half*)&raw;
        uint32_t base = VT_OFF + (uint32_t)(kv >> 6) * 8192u;
        int kcol = (kv & 63) * 2;
#pragma unroll
        for (int e = 0; e < 8; e++) {
            int d = c8 * 8 + e;
            *(__half*)(sm + base + sw128((uint32_t)(d * 128 + kcol))) = hv[e];
        }
    }
    __syncthreads();

    // ---- compute ------------------------------------------------------------
    int lmat = l >> 3, lrow = l & 7;
    int frow = ((lmat & 2) ? 8 : 0) + lrow;
    int fcol = (lmat & 1) * 16;
    int mrow = w * 16 + frow;

    uint32_t qf[4][4];
#pragma unroll
    for (int kk = 0; kk < 4; kk++) {
        uint32_t a = smb + QS_OFF + sw128((uint32_t)(mrow * 128 + kk * 32 + fcol));
        LDSM4(qf[kk], a);
    }

    float oacc[8][4];
#pragma unroll
    for (int i = 0; i < 8; i++)
#pragma unroll
        for (int j = 0; j < 4; j++) oacc[i][j] = 0.f;
    float rs0 = 0.f, rs1 = 0.f;

#pragma unroll
    for (int c = 0; c < 2; c++) {
        float sc[16][4];
#pragma unroll
        for (int i = 0; i < 16; i++)
#pragma unroll
            for (int j = 0; j < 4; j++) sc[i][j] = 0.f;

        // S = Q @ K^T for kv chunk [c*128, +128)
#pragma unroll
        for (int ng = 0; ng < 8; ng++) {
            int kvrow = c * 128 + ng * 16 + frow;
#pragma unroll
            for (int kk = 0; kk < 4; kk++) {
                uint32_t bf[4];
                uint32_t a = smb + KS_OFF + sw128((uint32_t)(kvrow * 128 + kk * 32 + fcol));
                LDSM4(bf, a);
                MMA_F16(sc[2 * ng],     qf[kk][0], qf[kk][2], qf[kk][1], qf[kk][3], bf[0], bf[1]);
                MMA_F16(sc[2 * ng + 1], qf[kk][0], qf[kk][2], qf[kk][1], qf[kk][3], bf[2], bf[3]);
            }
        }

        // softmax + store P (half)
        int r0 = w * 16 + (l >> 2);
#pragma unroll
        for (int nt = 0; nt < 16; nt++) {
            float p0 = __expf(sc[nt][0]);
            float p1 = __expf(sc[nt][1]);
            float p2 = __expf(sc[nt][2]);
            float p3 = __expf(sc[nt][3]);
            rs0 += p0 + p1;
            rs1 += p2 + p3;
            int kvl = nt * 8 + 2 * (l & 3);
            uint32_t bo = PS_OFF + (uint32_t)(kvl >> 6) * 16384u;
            int kc = (kvl & 63) * 2;
            *(__half2*)(sm + bo + sw128((uint32_t)(r0 * 128 + kc)))
                = __floats2half2_rn(p0, p1);
            *(__half2*)(sm + bo + sw128((uint32_t)((r0 + 8) * 128 + kc)))
                = __floats2half2_rn(p2, p3);
        }
        __syncwarp();

        // O += P @ V
        uint32_t pf[8][4];
#pragma unroll
        for (int kt = 0; kt < 8; kt++) {
            uint32_t a = smb + PS_OFF + (uint32_t)(kt >> 2) * 16384u
                       + sw128((uint32_t)(mrow * 128 + (kt & 3) * 32 + fcol));
            LDSM4(pf[kt], a);
        }
#pragma unroll
        for (int dg = 0; dg < 4; dg++) {
#pragma unroll
            for (int kt = 0; kt < 8; kt++) {
                uint32_t bf[4];
                uint32_t a = smb + VT_OFF + (uint32_t)(2 * c + (kt >> 2)) * 8192u
                           + sw128((uint32_t)((dg * 16 + frow) * 128 + (kt & 3) * 32 + fcol));
                LDSM4(bf, a);
                MMA_F16(oacc[2 * dg],     pf[kt][0], pf[kt][2], pf[kt][1], pf[kt][3], bf[0], bf[1]);
                MMA_F16(oacc[2 * dg + 1], pf[kt][0], pf[kt][2], pf[kt][1], pf[kt][3], bf[2], bf[3]);
            }
        }
        __syncwarp();
    }

    rs0 += __shfl_xor_sync(0xFFFFFFFFu, rs0, 1);
    rs0 += __shfl_xor_sync(0xFFFFFFFFu, rs0, 2);
    rs1 += __shfl_xor_sync(0xFFFFFFFFu, rs1, 1);
    rs1 += __shfl_xor_sync(0xFFFFFFFFu, rs1, 2);
    float inv0 = 1.0f / rs0, inv1 = 1.0f / rs1;

    int q0 = qt * 128 + w * 16 + (l >> 2);
    __half* o0 = O + ((size_t)(b * LQ_ + q0)) * D_ + h * HD_;
    __half* o1 = o0 + 8 * D_;
#pragma unroll
    for (int nt = 0; nt < 8; nt++) {
        int dcol = nt * 8 + 2 * (l & 3);
        *(__half2*)(o0 + dcol) = __floats2half2_rn(oacc[nt][0] * inv0, oacc[nt][1] * inv0);
        *(__half2*)(o1 + dcol) = __floats2half2_rn(oacc[nt][2] * inv1, oacc[nt][3] * inv1);
    }
}

// ---------------------------------------------------------------------------
extern "C" void kernel_launch(void* const* d_in, const int* in_sizes, int n_in,
                              void* d_out, int out_size)
{
    const float* patches = (const float*)d_in[0];
    const float* latents = (const float*)d_in[1];
    const float* Wq = (const float*)d_in[2];
    const float* bq = (const float*)d_in[3];
    const float* Wk = (const float*)d_in[4];
    const float* bk = (const float*)d_in[5];
    const float* Wv = (const float*)d_in[6];
    const float* bv = (const float*)d_in[7];
    const float* Wo = (const float*)d_in[8];
    const float* bo = (const float*)d_in[9];
    const int*   nf = (const int*)d_in[10];
    float* out = (float*)d_out;

    __half *Ph, *Lh, *Qd, *Kd, *Vd, *Ad, *WtQ, *WtK, *WtV, *WtO;
    cudaGetSymbolAddress((void**)&Ph,  g_Ph);
    cudaGetSymbolAddress((void**)&Lh,  g_Lh);
    cudaGetSymbolAddress((void**)&Qd,  g_Q);
    cudaGetSymbolAddress((void**)&Kd,  g_K);
    cudaGetSymbolAddress((void**)&Vd,  g_V);
    cudaGetSymbolAddress((void**)&Ad,  g_attn);
    cudaGetSymbolAddress((void**)&WtQ, g_WtQ);
    cudaGetSymbolAddress((void**)&WtK, g_WtK);
    cudaGetSymbolAddress((void**)&WtV, g_WtV);
    cudaGetSymbolAddress((void**)&WtO, g_WtO);

    cudaFuncSetAttribute(gemm_f16<__half>, cudaFuncAttributeMaxDynamicSharedMemorySize, GEMM_SMEM);
    cudaFuncSetAttribute(gemm_f16<float>,  cudaFuncAttributeMaxDynamicSharedMemorySize, GEMM_SMEM);
    cudaFuncSetAttribute(attn_kernel, cudaFuncAttributeMaxDynamicSharedMemorySize, ATTN_SMEM);

    // 0) prep
    dim3 tb(32, 8);
    transpose_kernel<<<dim3(D_ / 32, D_ / 32), tb>>>(Wq, WtQ, D_, D_);
    transpose_kernel<<<dim3((KVH_ * HD_) / 32, D_ / 32), tb>>>(Wk, WtK, D_, KVH_ * HD_);
    transpose_kernel<<<dim3((KVH_ * HD_) / 32, D_ / 32), tb>>>(Wv, WtV, D_, KVH_ * HD_);
    transpose_kernel<<<dim3(D_ / 32, D_ / 32), tb>>>(Wo, WtO, D_, D_);
    rope_table_kernel<<<(NF_MAX * 32) / 256, 256>>>(nf);
    int np4 = B_ * LQ_ * D_ / 4;
    cvt_f16_kernel<<<(np4 + 255) / 256, 256>>>(patches, Ph, np4);
    int nl4 = B_ * LKV_ * D_ / 4;
    cvt_f16_kernel<<<(nl4 + 255) / 256, 256>>>(latents, Lh, nl4);

    // 1) Q projection (half out)
    gemm_f16<__half><<<dim3(D_ / 128, (B_ * LQ_) / 128), 256, GEMM_SMEM>>>(
        Ph, WtQ, bq, Qd, B_ * LQ_, D_, D_);

    // 2) K / V projections (half out)
    gemm_f16<__half><<<dim3((KVH_ * HD_) / 128, (B_ * LKV_) / 128), 256, GEMM_SMEM>>>(
        Lh, WtK, bk, Kd, B_ * LKV_, KVH_ * HD_, D_);
    gemm_f16<__half><<<dim3((KVH_ * HD_) / 128, (B_ * LKV_) / 128), 256, GEMM_SMEM>>>(
        Lh, WtV, bv, Vd, B_ * LKV_, KVH_ * HD_, D_);

    // 3) attention (fp16 mma + fused RoPE) -> half g_attn
    dim3 ga(LQ_ / 128, H_, B_);
    attn_kernel<<<ga, 256, ATTN_SMEM>>>(Qd, Kd, Vd, Ad, nf);

    // 4) output projection (float out)
    gemm_f16<float><<<dim3(D_ / 128, (B_ * LQ_) / 128), 256, GEMM_SMEM>>>(
        Ad, WtO, bo, out, B_ * LQ_, D_, D_);
}

// round 9
// speedup vs baseline: 2.2827x; 1.0553x over previous
#include <cuda_runtime.h>
#include <cuda_fp16.h>
#include <math.h>
#include <stdint.h>

#define B_    4
#define LQ_   4096
#define LKV_  256
#define D_    1024
#define H_    16
#define KVH_  4
#define HD_   64
#define NF_MAX 4096

// ---------------- scratch (device globals; no allocation allowed) ----------
__device__ __half g_Ph[(size_t)B_ * LQ_ * D_];          // fp16 patches
__device__ __half g_Lh[(size_t)B_ * LKV_ * D_];         // fp16 latents
__device__ __half g_Q[(size_t)B_ * LQ_ * D_];           // fp16 Q
__device__ __half g_KV[(size_t)B_ * LKV_ * 512];        // fused K|V (row: kvh*64 | 256+kvh*64)
__device__ __half g_attn[(size_t)B_ * LQ_ * D_];        // fp16 attn out
__device__ __half g_WtQ[(size_t)D_ * D_];               // W^T [N][K] fp16
__device__ __half g_WtKV[(size_t)512 * D_];             // [Wk^T ; Wv^T]
__device__ __half g_WtO[(size_t)D_ * D_];
__device__ float  g_bkv[512];                            // bk | bv
__device__ float  g_rope[2 * NF_MAX * 32];              // cos | sin

// ---------------- helpers ---------------------------------------------------
__device__ __forceinline__ uint32_t smem_u32(const void* p) {
    uint32_t a;
    asm("{ .reg .u64 t; cvta.to.shared.u64 t, %1; cvt.u32.u64 %0, t; }"
        : "=r"(a) : "l"(p));
    return a;
}
__device__ __forceinline__ uint32_t sw128(uint32_t off) {
    return off ^ ((off >> 3) & 0x70);
}

#define CP_A16(d, s) \
    asm volatile("cp.async.cg.shared.global [%0], [%1], 16;" :: "r"(d), "l"(s) : "memory")
#define CP_COMMIT() asm volatile("cp.async.commit_group;" ::: "memory")
#define CP_WAIT1()  asm volatile("cp.async.wait_group 1;" ::: "memory")
#define CP_WAIT0()  asm volatile("cp.async.wait_group 0;" ::: "memory")
#define LDSM4(r, addr) \
    asm volatile("ldmatrix.sync.aligned.m8n8.x4.shared.b16 {%0,%1,%2,%3}, [%4];" \
        : "=r"((r)[0]), "=r"((r)[1]), "=r"((r)[2]), "=r"((r)[3]) : "r"(addr))
#define MMA_F16(d, a0, a1, a2, a3, b0, b1) \
    asm volatile("mma.sync.aligned.m16n8k16.row.col.f32.f16.f16.f32 " \
        "{%0,%1,%2,%3}, {%4,%5,%6,%7}, {%8,%9}, {%0,%1,%2,%3};" \
        : "+f"((d)[0]), "+f"((d)[1]), "+f"((d)[2]), "+f"((d)[3]) \
        : "r"(a0), "r"(a1), "r"(a2), "r"(a3), "r"(b0), "r"(b1))

__device__ __forceinline__ void store2(float* p, float x, float y) {
    *(float2*)p = make_float2(x, y);
}
__device__ __forceinline__ void store2(__half* p, float x, float y) {
    *(__half2*)p = __floats2half2_rn(x, y);
}

// ---------------------------------------------------------------------------
// Merged fp32->fp16 convert for patches + latents
// ---------------------------------------------------------------------------
__global__ void cvt_both_kernel(const float* __restrict__ p, const float* __restrict__ l,
                                __half* __restrict__ ph, __half* __restrict__ lh,
                                int np4, int ntot4)
{
    int i = blockIdx.x * blockDim.x + threadIdx.x;
    if (i >= ntot4) return;
    const float* in;
    __half* out;
    int j;
    if (i < np4) { in = p; out = ph; j = i; }
    else         { in = l; out = lh; j = i - np4; }
    float4 v = reinterpret_cast<const float4*>(in)[j];
    reinterpret_cast<__half2*>(out)[2 * j]     = __floats2half2_rn(v.x, v.y);
    reinterpret_cast<__half2*>(out)[2 * j + 1] = __floats2half2_rn(v.z, v.w);
}

// ---------------------------------------------------------------------------
// Batched weight transpose: z=0 Wq->WtQ, z=1 Wo->WtO, z=2 Wk|Wv->WtKV
// ---------------------------------------------------------------------------
__global__ void transpose_all_kernel(const float* __restrict__ Wq, const float* __restrict__ Wk,
                                     const float* __restrict__ Wv, const float* __restrict__ Wo,
                                     __half* __restrict__ WtQ, __half* __restrict__ WtKV,
                                     __half* __restrict__ WtO)
{
    __shared__ float t[32][33];
    int z = blockIdx.z;
    const float* W;
    __half* Wt;
    int N, nb, rowoff = 0;
    if (z == 0)      { W = Wq; Wt = WtQ; N = D_; nb = blockIdx.x * 32; }
    else if (z == 1) { W = Wo; Wt = WtO; N = D_; nb = blockIdx.x * 32; }
    else {
        if (blockIdx.x >= 16) return;
        if (blockIdx.x < 8) { W = Wk; rowoff = 0;   nb = blockIdx.x * 32; }
        else                { W = Wv; rowoff = 256; nb = (blockIdx.x - 8) * 32; }
        Wt = WtKV; N = KVH_ * HD_;
    }
    int kb = blockIdx.y * 32;
    int x = threadIdx.x, y = threadIdx.y;   // 32 x 8
#pragma unroll
    for (int i = 0; i < 32; i += 8)
        t[y + i][x] = W[(size_t)(kb + y + i) * N + nb + x];
    __syncthreads();
#pragma unroll
    for (int i = 0; i < 32; i += 8)
        Wt[(size_t)(rowoff + nb + y + i) * D_ + kb + x] = __float2half_rn(t[x][y + i]);
}

// ---------------------------------------------------------------------------
// RoPE table + bias concat (blocks 0/1 also copy bk/bv into g_bkv)
// ---------------------------------------------------------------------------
__global__ void rope_table_kernel(const int* __restrict__ nf_ptr,
                                  const float* __restrict__ bk, const float* __restrict__ bv)
{
    if (blockIdx.x == 0) g_bkv[threadIdx.x] = bk[threadIdx.x];
    if (blockIdx.x == 1) g_bkv[256 + threadIdx.x] = bv[threadIdx.x];
    int nf = *nf_ptr;
    if (nf <= 1 || nf > NF_MAX) return;
    int idx = blockIdx.x * blockDim.x + threadIdx.x;
    if (idx >= nf * 32) return;
    int j = idx & 31, pos = idx >> 5;
    float inv = powf(10000.0f, -(float)(2 * j) / 64.0f);
    float th = (float)pos * inv;
    g_rope[idx] = cosf(th);
    g_rope[NF_MAX * 32 + idx] = sinf(th);
}

// ---------------------------------------------------------------------------
// fp16 mma.sync GEMM (proven R7 mainloop): C = A @ Bt^T + bias
// CTA 128x128, 256 thr (8 warps, 64x32), BK=64 halves, 2-stage cp.async.
// ---------------------------------------------------------------------------
#define GEMM_SMEM (1024 + 4 * 16384)

__device__ __forceinline__ void load_tile(const __half* Ag, const __half* Bg, int K,
                                          uint32_t aBuf, uint32_t bBuf, int tid)
{
#pragma unroll
    for (int j = 0; j < 4; j++) {
        int idx = j * 256 + tid;
        int row = idx >> 3, k8 = idx & 7;
        uint32_t off = sw128((uint32_t)(row * 128 + k8 * 16));
        CP_A16(aBuf + off, Ag + (size_t)row * K + k8 * 8);
        CP_A16(bBuf + off, Bg + (size_t)row * K + k8 * 8);
    }
}

template <typename OutT>
__global__ __launch_bounds__(256)
void gemm_f16(const __half* __restrict__ A, const __half* __restrict__ Bt,
              const float* __restrict__ bias, OutT* __restrict__ C,
              int M, int N, int K)
{
    extern __shared__ char smraw[];
    uint32_t base = smem_u32(smraw);
    uint32_t data = (base + 1023u) & ~1023u;

    int tid = threadIdx.x, lane = tid & 31, wid = tid >> 5;
    int wm = (wid >> 2) * 64;
    int wn = (wid & 3) * 32;

    const __half* Ag = A  + (size_t)blockIdx.y * 128 * K;
    const __half* Bg = Bt + (size_t)blockIdx.x * 128 * K;

    float acc[4][4][4];
#pragma unroll
    for (int i = 0; i < 4; i++)
#pragma unroll
        for (int j = 0; j < 4; j++)
#pragma unroll
            for (int k = 0; k < 4; k++) acc[i][j][k] = 0.f;

    int T = K >> 6;
    load_tile(Ag, Bg, K, data, data + 16384u, tid);
    CP_COMMIT();

    int lmat = lane >> 3, lrow = lane & 7;
    int frow = ((lmat & 2) ? 8 : 0) + lrow;
    int fcol = (lmat & 1) * 16;

    for (int t = 0; t < T; ++t) {
        int st = t & 1;
        if (t + 1 < T) {
            uint32_t nb = data + (uint32_t)((t + 1) & 1) * 32768u;
            load_tile(Ag + (t + 1) * 64, Bg + (t + 1) * 64, K, nb, nb + 16384u, tid);
            CP_COMMIT();
            CP_WAIT1();
        } else {
            CP_WAIT0();
        }
        __syncthreads();

        uint32_t aB = data + (uint32_t)st * 32768u;
        uint32_t bB = aB + 16384u;
#pragma unroll
        for (int kk = 0; kk < 4; ++kk) {
            uint32_t af[4][4], bf[2][4];
#pragma unroll
            for (int mi = 0; mi < 4; ++mi) {
                uint32_t addr = aB + sw128((uint32_t)((wm + mi * 16 + frow) * 128 + kk * 32 + fcol));
                LDSM4(af[mi], addr);
            }
#pragma unroll
            for (int nj = 0; nj < 2; ++nj) {
                uint32_t addr = bB + sw128((uint32_t)((wn + nj * 16 + frow) * 128 + kk * 32 + fcol));
                LDSM4(bf[nj], addr);
            }
#pragma unroll
            for (int mi = 0; mi < 4; ++mi)
#pragma unroll
                for (int ni = 0; ni < 4; ++ni) {
                    int nj = ni >> 1, lh = (ni & 1) * 2;
                    MMA_F16(acc[mi][ni],
                            af[mi][0], af[mi][2], af[mi][1], af[mi][3],
                            bf[nj][lh], bf[nj][lh + 1]);
                }
        }
        __syncthreads();
    }

    int rbase = blockIdx.y * 128 + wm + (lane >> 2);
    int cbase = blockIdx.x * 128 + wn + (lane & 3) * 2;
#pragma unroll
    for (int mi = 0; mi < 4; ++mi) {
#pragma unroll
        for (int ni = 0; ni < 4; ++ni) {
            int c = cbase + ni * 8;
            float2 bv = *(const float2*)(bias + c);
            int r0 = rbase + mi * 16;
            store2(C + (size_t)r0 * N + c, acc[mi][ni][0] + bv.x, acc[mi][ni][1] + bv.y);
            store2(C + (size_t)(r0 + 8) * N + c, acc[mi][ni][2] + bv.x, acc[mi][ni][3] + bv.y);
        }
    }
}

// ---------------------------------------------------------------------------
// fp16 MMA flash attention with fused RoPE (R8 proven; KV fused layout).
// KV row layout: [kvh*64 .. +64) = K head, [256 + kvh*64 ..) = V head.
// ---------------------------------------------------------------------------
#define QS_OFF 0u
#define KS_OFF 16384u
#define VT_OFF 49152u
#define PS_OFF 81920u
#define ATTN_SMEM 114688

__global__ __launch_bounds__(256)
void attn_kernel(const __half* __restrict__ Q, const __half* __restrict__ KV,
                 __half* __restrict__ O, const int* __restrict__ nf_ptr)
{
    extern __shared__ char sm[];
    uint32_t smb = smem_u32(sm);

    int tid = threadIdx.x, l = tid & 31, w = tid >> 5;
    int b = blockIdx.z, h = blockIdx.y, qt = blockIdx.x;
    int kvh = h >> 2;
    int nf = *nf_ptr;
    bool rope = (nf > 1) && (nf <= NF_MAX);
    int qdiv = rope ? (LQ_ / nf) : 1;
    int kdiv = rope ? (LKV_ / nf) : 1;

    // ---- Q tile: rope + scale ----------------------------------------------
    {
        int row = tid >> 1, part = tid & 1;
        int qglob = qt * 128 + row;
        const __half* src = Q + ((size_t)(b * LQ_ + qglob)) * D_ + h * HD_;
        int pos = rope ? (qglob / qdiv) : 0;
        const float* ct = g_rope + pos * 32;
        const float* st = g_rope + NF_MAX * 32 + pos * 32;
#pragma unroll
        for (int jj = 0; jj < 4; jj++) {
            int j = part * 16 + jj * 4;
            __half2 u0 = *(const __half2*)(src + j);
            __half2 u1 = *(const __half2*)(src + j + 2);
            __half2 v0 = *(const __half2*)(src + j + 32);
            __half2 v1 = *(const __half2*)(src + j + 34);
            float a1[4] = { __low2float(u0), __high2float(u0), __low2float(u1), __high2float(u1) };
            float a2[4] = { __low2float(v0), __high2float(v0), __low2float(v1), __high2float(v1) };
            float y1[4], y2[4];
#pragma unroll
            for (int e = 0; e < 4; e++) {
                float c = 1.f, s = 0.f;
                if (rope) { c = ct[j + e], s = st[j + e]; }
                y1[e] = (a1[e] * c - a2[e] * s) * 0.125f;
                y2[e] = (a2[e] * c + a1[e] * s) * 0.125f;
            }
            uint32_t o0 = QS_OFF + sw128((uint32_t)(row * 128 + j * 2));
            uint32_t o1 = QS_OFF + sw128((uint32_t)(row * 128 + (j + 32) * 2));
            ((__half2*)(sm + o0))[0] = __floats2half2_rn(y1[0], y1[1]);
            ((__half2*)(sm + o0))[1] = __floats2half2_rn(y1[2], y1[3]);
            ((__half2*)(sm + o1))[0] = __floats2half2_rn(y2[0], y2[1]);
            ((__half2*)(sm + o1))[1] = __floats2half2_rn(y2[2], y2[3]);
        }
    }

    // ---- K tile: rope -------------------------------------------------------
#pragma unroll
    for (int u = tid; u < 512; u += 256) {
        int row = u >> 1, part = u & 1;
        const __half* src = KV + (size_t)(b * LKV_ + row) * 512 + kvh * HD_;
        int pos = rope ? (row / kdiv) : 0;
        const float* ct = g_rope + pos * 32;
        const float* st = g_rope + NF_MAX * 32 + pos * 32;
#pragma unroll
        for (int jj = 0; jj < 4; jj++) {
            int j = part * 16 + jj * 4;
            __half2 u0 = *(const __half2*)(src + j);
            __half2 u1 = *(const __half2*)(src + j + 2);
            __half2 v0 = *(const __half2*)(src + j + 32);
            __half2 v1 = *(const __half2*)(src + j + 34);
            float a1[4] = { __low2float(u0), __high2float(u0), __low2float(u1), __high2float(u1) };
            float a2[4] = { __low2float(v0), __high2float(v0), __low2float(v1), __high2float(v1) };
            float y1[4], y2[4];
#pragma unroll
            for (int e = 0; e < 4; e++) {
                float c = 1.f, s = 0.f;
                if (rope) { c = ct[j + e], s = st[j + e]; }
                y1[e] = a1[e] * c - a2[e] * s;
                y2[e] = a2[e] * c + a1[e] * s;
            }
            uint32_t o0 = KS_OFF + sw128((uint32_t)(row * 128 + j * 2));
            uint32_t o1 = KS_OFF + sw128((uint32_t)(row * 128 + (j + 32) * 2));
            ((__half2*)(sm + o0))[0] = __floats2half2_rn(y1[0], y1[1]);
            ((__half2*)(sm + o0))[1] = __floats2half2_rn(y1[2], y1[3]);
            ((__half2*)(sm + o1))[0] = __floats2half2_rn(y2[0], y2[1]);
            ((__half2*)(sm + o1))[1] = __floats2half2_rn(y2[2], y2[3]);
        }
    }

    // ---- V transposed -------------------------------------------------------
#pragma unroll
    for (int it = 0; it < 8; it++) {
        int idx = it * 256 + tid;
        int kv = idx >> 3, c8 = idx & 7;
        const __half* src = KV + (size_t)(b * LKV_ + kv) * 512 + 256 + kvh * HD_ + c8 * 8;
        uint4 raw = *(const uint4*)src;
        const __half* hv = (const __half*)&raw;
        uint32_t base = VT_OFF + (uint32_t)(kv >> 6) * 8192u;
        int kcol = (kv & 63) * 2;
#pragma unroll
        for (int e = 0; e < 8; e++) {
            int d = c8 * 8 + e;
            *(__half*)(sm + base + sw128((uint32_t)(d * 128 + kcol))) = hv[e];
        }
    }
    __syncthreads();

    // ---- compute ------------------------------------------------------------
    int lmat = l >> 3, lrow = l & 7;
    int frow = ((lmat & 2) ? 8 : 0) + lrow;
    int fcol = (lmat & 1) * 16;
    int mrow = w * 16 + frow;

    uint32_t qf[4][4];
#pragma unroll
    for (int kk = 0; kk < 4; kk++) {
        uint32_t a = smb + QS_OFF + sw128((uint32_t)(mrow * 128 + kk * 32 + fcol));
        LDSM4(qf[kk], a);
    }

    float oacc[8][4];
#pragma unroll
    for (int i = 0; i < 8; i++)
#pragma unroll
        for (int j = 0; j < 4; j++) oacc[i][j] = 0.f;
    float rs0 = 0.f, rs1 = 0.f;

#pragma unroll
    for (int c = 0; c < 2; c++) {
        float sc[16][4];
#pragma unroll
        for (int i = 0; i < 16; i++)
#pragma unroll
            for (int j = 0; j < 4; j++) sc[i][j] = 0.f;

#pragma unroll
        for (int ng = 0; ng < 8; ng++) {
            int kvrow = c * 128 + ng * 16 + frow;
#pragma unroll
            for (int kk = 0; kk < 4; kk++) {
                uint32_t bf[4];
                uint32_t a = smb + KS_OFF + sw128((uint32_t)(kvrow * 128 + kk * 32 + fcol));
                LDSM4(bf, a);
                MMA_F16(sc[2 * ng],     qf[kk][0], qf[kk][2], qf[kk][1], qf[kk][3], bf[0], bf[1]);
                MMA_F16(sc[2 * ng + 1], qf[kk][0], qf[kk][2], qf[kk][1], qf[kk][3], bf[2], bf[3]);
            }
        }

        int r0 = w * 16 + (l >> 2);
#pragma unroll
        for (int nt = 0; nt < 16; nt++) {
            float p0 = __expf(sc[nt][0]);
            float p1 = __expf(sc[nt][1]);
            float p2 = __expf(sc[nt][2]);
            float p3 = __expf(sc[nt][3]);
            rs0 += p0 + p1;
            rs1 += p2 + p3;
            int kvl = nt * 8 + 2 * (l & 3);
            uint32_t bo = PS_OFF + (uint32_t)(kvl >> 6) * 16384u;
            int kc = (kvl & 63) * 2;
            *(__half2*)(sm + bo + sw128((uint32_t)(r0 * 128 + kc)))
                = __floats2half2_rn(p0, p1);
            *(__half2*)(sm + bo + sw128((uint32_t)((r0 + 8) * 128 + kc)))
                = __floats2half2_rn(p2, p3);
        }
        __syncwarp();

        uint32_t pf[8][4];
#pragma unroll
        for (int kt = 0; kt < 8; kt++) {
            uint32_t a = smb + PS_OFF + (uint32_t)(kt >> 2) * 16384u
                       + sw128((uint32_t)(mrow * 128 + (kt & 3) * 32 + fcol));
            LDSM4(pf[kt], a);
        }
#pragma unroll
        for (int dg = 0; dg < 4; dg++) {
#pragma unroll
            for (int kt = 0; kt < 8; kt++) {
                uint32_t bf[4];
                uint32_t a = smb + VT_OFF + (uint32_t)(2 * c + (kt >> 2)) * 8192u
                           + sw128((uint32_t)((dg * 16 + frow) * 128 + (kt & 3) * 32 + fcol));
                LDSM4(bf, a);
                MMA_F16(oacc[2 * dg],     pf[kt][0], pf[kt][2], pf[kt][1], pf[kt][3], bf[0], bf[1]);
                MMA_F16(oacc[2 * dg + 1], pf[kt][0], pf[kt][2], pf[kt][1], pf[kt][3], bf[2], bf[3]);
            }
        }
        __syncwarp();
    }

    rs0 += __shfl_xor_sync(0xFFFFFFFFu, rs0, 1);
    rs0 += __shfl_xor_sync(0xFFFFFFFFu, rs0, 2);
    rs1 += __shfl_xor_sync(0xFFFFFFFFu, rs1, 1);
    rs1 += __shfl_xor_sync(0xFFFFFFFFu, rs1, 2);
    float inv0 = 1.0f / rs0, inv1 = 1.0f / rs1;

    int q0 = qt * 128 + w * 16 + (l >> 2);
    __half* o0 = O + ((size_t)(b * LQ_ + q0)) * D_ + h * HD_;
    __half* o1 = o0 + 8 * D_;
#pragma unroll
    for (int nt = 0; nt < 8; nt++) {
        int dcol = nt * 8 + 2 * (l & 3);
        *(__half2*)(o0 + dcol) = __floats2half2_rn(oacc[nt][0] * inv0, oacc[nt][1] * inv0);
        *(__half2*)(o1 + dcol) = __floats2half2_rn(oacc[nt][2] * inv1, oacc[nt][3] * inv1);
    }
}

// ---------------------------------------------------------------------------
extern "C" void kernel_launch(void* const* d_in, const int* in_sizes, int n_in,
                              void* d_out, int out_size)
{
    const float* patches = (const float*)d_in[0];
    const float* latents = (const float*)d_in[1];
    const float* Wq = (const float*)d_in[2];
    const float* bq = (const float*)d_in[3];
    const float* Wk = (const float*)d_in[4];
    const float* bk = (const float*)d_in[5];
    const float* Wv = (const float*)d_in[6];
    const float* bv = (const float*)d_in[7];
    const float* Wo = (const float*)d_in[8];
    const float* bo = (const float*)d_in[9];
    const int*   nf = (const int*)d_in[10];
    float* out = (float*)d_out;

    __half *Ph, *Lh, *Qd, *KVd, *Ad, *WtQ, *WtKV, *WtO;
    float *bkv;
    cudaGetSymbolAddress((void**)&Ph,   g_Ph);
    cudaGetSymbolAddress((void**)&Lh,   g_Lh);
    cudaGetSymbolAddress((void**)&Qd,   g_Q);
    cudaGetSymbolAddress((void**)&KVd,  g_KV);
    cudaGetSymbolAddress((void**)&Ad,   g_attn);
    cudaGetSymbolAddress((void**)&WtQ,  g_WtQ);
    cudaGetSymbolAddress((void**)&WtKV, g_WtKV);
    cudaGetSymbolAddress((void**)&WtO,  g_WtO);
    cudaGetSymbolAddress((void**)&bkv,  g_bkv);

    cudaFuncSetAttribute(gemm_f16<__half>, cudaFuncAttributeMaxDynamicSharedMemorySize, GEMM_SMEM);
    cudaFuncSetAttribute(gemm_f16<float>,  cudaFuncAttributeMaxDynamicSharedMemorySize, GEMM_SMEM);
    cudaFuncSetAttribute(attn_kernel, cudaFuncAttributeMaxDynamicSharedMemorySize, ATTN_SMEM);

    // 0) prep (3 launches)
    transpose_all_kernel<<<dim3(32, 32, 3), dim3(32, 8)>>>(Wq, Wk, Wv, Wo, WtQ, WtKV, WtO);
    rope_table_kernel<<<(NF_MAX * 32) / 256, 256>>>(nf, bk, bv);
    int np4 = B_ * LQ_ * D_ / 4;
    int nl4 = B_ * LKV_ * D_ / 4;
    cvt_both_kernel<<<(np4 + nl4 + 255) / 256, 256>>>(patches, latents, Ph, Lh, np4, np4 + nl4);

    // 1) Q projection (half out)
    gemm_f16<__half><<<dim3(D_ / 128, (B_ * LQ_) / 128), 256, GEMM_SMEM>>>(
        Ph, WtQ, bq, Qd, B_ * LQ_, D_, D_);

    // 2) fused K|V projection (half out, N=512)
    gemm_f16<__half><<<dim3(512 / 128, (B_ * LKV_) / 128), 256, GEMM_SMEM>>>(
        Lh, WtKV, bkv, KVd, B_ * LKV_, 512, D_);

    // 3) attention (fp16 mma + fused RoPE)
    dim3 ga(LQ_ / 128, H_, B_);
    attn_kernel<<<ga, 256, ATTN_SMEM>>>(Qd, KVd, Ad, nf);

    // 4) output projection (float out)
    gemm_f16<float><<<dim3(D_ / 128, (B_ * LQ_) / 128), 256, GEMM_SMEM>>>(
        Ad, WtO, bo, out, B_ * LQ_, D_, D_);
}